// round 2
// baseline (speedup 1.0000x reference)
#include <cuda_runtime.h>
#include <math.h>
#include <stdint.h>

// Problem constants
#define BATCH 8
#define SEQL  1024
#define TOK   (BATCH*SEQL)     // 8192
#define DMODEL 768
#define NHEAD 12
#define DKHEAD 64
#define FFDIM 3072
#define NLAYER 6
#define NCLS  10

// ----------------------------------------------------------------------------
// Scratch (device globals — no runtime allocation allowed)
// ----------------------------------------------------------------------------
__device__ float g_x  [TOK * DMODEL];   // residual stream
__device__ float g_q  [TOK * DMODEL];
__device__ float g_k  [TOK * DMODEL];
__device__ float g_v  [TOK * DMODEL];
__device__ float g_att[TOK * DMODEL];   // attention output (pre O-proj)
__device__ float g_tmp[TOK * DMODEL];   // projection outputs pre-residual
__device__ float g_ff [TOK * FFDIM];    // FFN hidden

// ----------------------------------------------------------------------------
// Embedding + sinusoidal PE
// ----------------------------------------------------------------------------
__global__ void __launch_bounds__(256) embed_kernel(const int* __restrict__ ids,
                                                    const float* __restrict__ emb)
{
    int t = blockIdx.x;              // token index (b*L + l)
    int pos = t & (SEQL - 1);        // l
    const float* e = emb + (size_t)ids[t] * DMODEL;
    size_t base = (size_t)t * DMODEL;
    const float klog = -9.210340371976184f / (float)DMODEL;  // -ln(10000)/D
    for (int d = threadIdx.x; d < DMODEL; d += 256) {
        int i2 = d & ~1;
        float freq = expf((float)i2 * klog);
        float ang = (float)pos * freq;
        float pe = (d & 1) ? cosf(ang) : sinf(ang);
        g_x[base + d] = e[d] + pe;
    }
}

// ----------------------------------------------------------------------------
// SGEMM: C[M,N] = A[M,K] @ W[K,N] + bias[N]   (optional ReLU)
// Tiles: BM=128, BN=128, BK=16; 256 threads; 8x8 micro-tile per thread.
// M,N multiples of 128; K multiple of 16 (true for all shapes here).
// ----------------------------------------------------------------------------
template<int RELU>
__device__ __forceinline__ void sgemm_body(
    const float* __restrict__ A, const float* __restrict__ W,
    const float* __restrict__ bias, float* __restrict__ C,
    int M, int N, int K, int bx, int by)
{
    __shared__ float As[16][128];
    __shared__ float Bs[16][128];

    const int tid = threadIdx.x;
    const int trow = tid >> 4;   // 0..15
    const int tcol = tid & 15;   // 0..15

    // A-tile loads: 128 rows x 16 k -> 512 float4, 2 per thread (rows r, r+64)
    const int arow = tid >> 2;            // 0..63
    const int aseg = (tid & 3) * 4;       // k sub-offset 0,4,8,12
    const float* Ap0 = A + (size_t)(by * 128 + arow) * K + aseg;
    const float* Ap1 = Ap0 + (size_t)64 * K;

    // B-tile loads: 16 k-rows x 128 cols -> 512 float4, 2 per thread
    const int brow = tid >> 5;            // 0..7
    const int bcol = (tid & 31) * 4;      // 0..124
    const float* Bp0 = W + (size_t)brow * N + bx * 128 + bcol;
    const float* Bp1 = Bp0 + (size_t)8 * N;

    float acc[8][8];
#pragma unroll
    for (int i = 0; i < 8; i++)
#pragma unroll
        for (int j = 0; j < 8; j++) acc[i][j] = 0.f;

    for (int k0 = 0; k0 < K; k0 += 16) {
        float4 a0 = *(const float4*)(Ap0 + k0);
        float4 a1 = *(const float4*)(Ap1 + k0);
        float4 b0 = *(const float4*)(Bp0 + (size_t)k0 * N);
        float4 b1 = *(const float4*)(Bp1 + (size_t)k0 * N);
        __syncthreads();
        As[aseg + 0][arow] = a0.x;  As[aseg + 1][arow] = a0.y;
        As[aseg + 2][arow] = a0.z;  As[aseg + 3][arow] = a0.w;
        As[aseg + 0][64 + arow] = a1.x;  As[aseg + 1][64 + arow] = a1.y;
        As[aseg + 2][64 + arow] = a1.z;  As[aseg + 3][64 + arow] = a1.w;
        *(float4*)&Bs[brow][bcol]     = b0;
        *(float4*)&Bs[8 + brow][bcol] = b1;
        __syncthreads();
#pragma unroll
        for (int kk = 0; kk < 16; kk++) {
            float4 af0 = *(const float4*)&As[kk][trow * 4];
            float4 af1 = *(const float4*)&As[kk][64 + trow * 4];
            float4 bf0 = *(const float4*)&Bs[kk][tcol * 4];
            float4 bf1 = *(const float4*)&Bs[kk][64 + tcol * 4];
            float av[8] = {af0.x, af0.y, af0.z, af0.w, af1.x, af1.y, af1.z, af1.w};
            float bv[8] = {bf0.x, bf0.y, bf0.z, bf0.w, bf1.x, bf1.y, bf1.z, bf1.w};
#pragma unroll
            for (int i = 0; i < 8; i++)
#pragma unroll
                for (int j = 0; j < 8; j++)
                    acc[i][j] = fmaf(av[i], bv[j], acc[i][j]);
        }
    }

    const int colb = bx * 128;
    const int rowb = by * 128;
#pragma unroll
    for (int i = 0; i < 8; i++) {
        int row = rowb + ((i < 4) ? (trow * 4 + i) : (64 + trow * 4 + (i - 4)));
        float* Crow = C + (size_t)row * N + colb;
#pragma unroll
        for (int jh = 0; jh < 2; jh++) {
            int c0 = (jh == 0) ? (tcol * 4) : (64 + tcol * 4);
            float4 bb = *(const float4*)(bias + colb + c0);
            float4 r;
            r.x = acc[i][jh * 4 + 0] + bb.x;
            r.y = acc[i][jh * 4 + 1] + bb.y;
            r.z = acc[i][jh * 4 + 2] + bb.z;
            r.w = acc[i][jh * 4 + 3] + bb.w;
            if (RELU) {
                r.x = fmaxf(r.x, 0.f); r.y = fmaxf(r.y, 0.f);
                r.z = fmaxf(r.z, 0.f); r.w = fmaxf(r.w, 0.f);
            }
            *(float4*)(Crow + c0) = r;
        }
    }
}

template<int RELU>
__global__ void __launch_bounds__(256) sgemm_bias(
    const float* __restrict__ A, const float* __restrict__ W,
    const float* __restrict__ bias, float* __restrict__ C,
    int M, int N, int K)
{
    sgemm_body<RELU>(A, W, bias, C, M, N, K, blockIdx.x, blockIdx.y);
}

// Fused Q/K/V projection: blockIdx.z selects which of the three GEMMs.
__global__ void __launch_bounds__(256) sgemm_qkv(
    const float* __restrict__ A,
    const float* __restrict__ Wq, const float* __restrict__ Bq,
    const float* __restrict__ Wk, const float* __restrict__ Bk,
    const float* __restrict__ Wv, const float* __restrict__ Bv,
    float* __restrict__ Cq, float* __restrict__ Ck, float* __restrict__ Cv)
{
    const float* W; const float* bias; float* C;
    if (blockIdx.z == 0)      { W = Wq; bias = Bq; C = Cq; }
    else if (blockIdx.z == 1) { W = Wk; bias = Bk; C = Ck; }
    else                      { W = Wv; bias = Bv; C = Cv; }
    sgemm_body<0>(A, W, bias, C, TOK, DMODEL, DMODEL, blockIdx.x, blockIdx.y);
}

// ----------------------------------------------------------------------------
// Attention (flash-style): one block = (b,h, 64 query rows); one thread = one row.
// Q pre-scaled by 1/sqrt(64). Online softmax in chunks of 8 keys.
// ----------------------------------------------------------------------------
__global__ void __launch_bounds__(64) attn_kernel(const int* __restrict__ mask)
{
    const int b = blockIdx.x / NHEAD;
    const int h = blockIdx.x % NHEAD;
    const int l = blockIdx.y * 64 + threadIdx.x;

    float q[DKHEAD];
    const float* qp = g_q + ((size_t)(b * SEQL + l)) * DMODEL + h * DKHEAD;
#pragma unroll
    for (int i = 0; i < DKHEAD; i++) q[i] = qp[i] * 0.125f;

    float o[DKHEAD];
#pragma unroll
    for (int i = 0; i < DKHEAD; i++) o[i] = 0.f;
    float m = -1e30f, ssum = 0.f;

    __shared__ float Ks[64][DKHEAD];
    __shared__ float Vs[64][DKHEAD];
    __shared__ float neg[64];

    for (int kt = 0; kt < SEQL / 64; kt++) {
        __syncthreads();
        int krow = kt * 64 + threadIdx.x;
        const float* kp = g_k + ((size_t)(b * SEQL + krow)) * DMODEL + h * DKHEAD;
        const float* vp = g_v + ((size_t)(b * SEQL + krow)) * DMODEL + h * DKHEAD;
#pragma unroll
        for (int i = 0; i < DKHEAD / 4; i++) {
            ((float4*)Ks[threadIdx.x])[i] = ((const float4*)kp)[i];
            ((float4*)Vs[threadIdx.x])[i] = ((const float4*)vp)[i];
        }
        neg[threadIdx.x] = (mask[b * SEQL + krow] == 0) ? -1e9f : 0.f;
        __syncthreads();

#pragma unroll
        for (int c = 0; c < 8; c++) {           // 8 chunks of 8 keys
            float s[8];
            float cmax = -1e30f;
#pragma unroll
            for (int j = 0; j < 8; j++) {
                int jj = c * 8 + j;
                float acc = 0.f;
#pragma unroll
                for (int i = 0; i < DKHEAD; i += 4) {
                    float4 kv = *(const float4*)&Ks[jj][i];
                    acc = fmaf(q[i], kv.x, acc);
                    acc = fmaf(q[i + 1], kv.y, acc);
                    acc = fmaf(q[i + 2], kv.z, acc);
                    acc = fmaf(q[i + 3], kv.w, acc);
                }
                s[j] = acc + neg[jj];
                cmax = fmaxf(cmax, s[j]);
            }
            float nm = fmaxf(m, cmax);
            float corr = __expf(m - nm);
            m = nm;
            ssum *= corr;
#pragma unroll
            for (int i = 0; i < DKHEAD; i++) o[i] *= corr;
#pragma unroll
            for (int j = 0; j < 8; j++) {
                float p = __expf(s[j] - m);
                ssum += p;
#pragma unroll
                for (int i = 0; i < DKHEAD; i += 4) {
                    float4 vv = *(const float4*)&Vs[c * 8 + j][i];
                    o[i]     = fmaf(p, vv.x, o[i]);
                    o[i + 1] = fmaf(p, vv.y, o[i + 1]);
                    o[i + 2] = fmaf(p, vv.z, o[i + 2]);
                    o[i + 3] = fmaf(p, vv.w, o[i + 3]);
                }
            }
        }
    }

    float inv = 1.f / ssum;
    float* op = g_att + ((size_t)(b * SEQL + l)) * DMODEL + h * DKHEAD;
#pragma unroll
    for (int i = 0; i < DKHEAD; i += 4) {
        float4 r = make_float4(o[i] * inv, o[i + 1] * inv, o[i + 2] * inv, o[i + 3] * inv);
        *(float4*)(op + i) = r;
    }
}

// ----------------------------------------------------------------------------
// Residual add + LayerNorm (in-place into g_x). One block per token.
// ----------------------------------------------------------------------------
__global__ void __launch_bounds__(256) add_ln_kernel(const float* __restrict__ y,
                                                     const float* __restrict__ gam,
                                                     const float* __restrict__ bet)
{
    int t = blockIdx.x;
    __shared__ float red[32];
    size_t base = (size_t)t * DMODEL;

    float zr[3];
    float s = 0.f;
#pragma unroll
    for (int r = 0; r < 3; r++) {
        int d = threadIdx.x + r * 256;
        float v = g_x[base + d] + y[base + d];
        zr[r] = v; s += v;
    }
#pragma unroll
    for (int off = 16; off; off >>= 1) s += __shfl_xor_sync(0xffffffffu, s, off);
    if ((threadIdx.x & 31) == 0) red[threadIdx.x >> 5] = s;
    __syncthreads();
    if (threadIdx.x < 32) {
        float v = (threadIdx.x < 8) ? red[threadIdx.x] : 0.f;
#pragma unroll
        for (int off = 4; off; off >>= 1) v += __shfl_xor_sync(0xffffffffu, v, off);
        if (threadIdx.x == 0) red[0] = v;
    }
    __syncthreads();
    float mu = red[0] * (1.f / DMODEL);
    __syncthreads();

    float sq = 0.f;
#pragma unroll
    for (int r = 0; r < 3; r++) { float dz = zr[r] - mu; sq = fmaf(dz, dz, sq); }
#pragma unroll
    for (int off = 16; off; off >>= 1) sq += __shfl_xor_sync(0xffffffffu, sq, off);
    if ((threadIdx.x & 31) == 0) red[threadIdx.x >> 5] = sq;
    __syncthreads();
    if (threadIdx.x < 32) {
        float v = (threadIdx.x < 8) ? red[threadIdx.x] : 0.f;
#pragma unroll
        for (int off = 4; off; off >>= 1) v += __shfl_xor_sync(0xffffffffu, v, off);
        if (threadIdx.x == 0) red[0] = v;
    }
    __syncthreads();
    float rstd = rsqrtf(red[0] * (1.f / DMODEL) + 1e-5f);
#pragma unroll
    for (int r = 0; r < 3; r++) {
        int d = threadIdx.x + r * 256;
        g_x[base + d] = (zr[r] - mu) * rstd * gam[d] + bet[d];
    }
}

// ----------------------------------------------------------------------------
// Classifier: out[b,c] = x[b, token 0, :] @ cls_w + cls_b
// ----------------------------------------------------------------------------
__global__ void cls_kernel(const float* __restrict__ w,
                           const float* __restrict__ cb,
                           float* __restrict__ out)
{
    int t = threadIdx.x;
    if (t >= BATCH * NCLS) return;
    int b = t / NCLS, c = t % NCLS;
    const float* xp = g_x + (size_t)b * SEQL * DMODEL;   // token 0 of batch b
    float s = cb[c];
    for (int d = 0; d < DMODEL; d++) s = fmaf(xp[d], w[d * NCLS + c], s);
    out[t] = s;
}

// ----------------------------------------------------------------------------
// Launch
// ----------------------------------------------------------------------------
static float* sym_addr(const void* symbol)
{
    void* p = nullptr;
    cudaGetSymbolAddress(&p, symbol);
    return (float*)p;
}

extern "C" void kernel_launch(void* const* d_in, const int* in_sizes, int n_in,
                              void* d_out, int out_size)
{
    (void)in_sizes; (void)n_in; (void)out_size;
    const int*   ids  = (const int*)d_in[0];
    const int*   mask = (const int*)d_in[1];
    const float* emb  = (const float*)d_in[2];
    const float* wq = (const float*)d_in[3],  *bq = (const float*)d_in[4];
    const float* wk = (const float*)d_in[5],  *bk = (const float*)d_in[6];
    const float* wv = (const float*)d_in[7],  *bv = (const float*)d_in[8];
    const float* wo = (const float*)d_in[9],  *bo = (const float*)d_in[10];
    const float* g1 = (const float*)d_in[11], *bb1 = (const float*)d_in[12];
    const float* w1 = (const float*)d_in[13], *b1 = (const float*)d_in[14];
    const float* w2 = (const float*)d_in[15], *b2 = (const float*)d_in[16];
    const float* g2 = (const float*)d_in[17], *bb2 = (const float*)d_in[18];
    const float* cw = (const float*)d_in[19], *cb = (const float*)d_in[20];
    float* out = (float*)d_out;

    float* px   = sym_addr(g_x);
    float* pq   = sym_addr(g_q);
    float* pk   = sym_addr(g_k);
    float* pv   = sym_addr(g_v);
    float* patt = sym_addr(g_att);
    float* ptmp = sym_addr(g_tmp);
    float* pff  = sym_addr(g_ff);

    embed_kernel<<<TOK, 256>>>(ids, emb);

    dim3 gD(DMODEL / 128, TOK / 128);       // (6, 64)
    dim3 gQKV(DMODEL / 128, TOK / 128, 3);  // (6, 64, 3)
    dim3 gF(FFDIM / 128, TOK / 128);        // (24, 64)
    dim3 gA(BATCH * NHEAD, SEQL / 64);      // (96, 16)

    for (int l = 0; l < NLAYER; l++) {
        size_t oD = (size_t)l * DMODEL * DMODEL;
        size_t oF = (size_t)l * DMODEL * FFDIM;

        sgemm_qkv<<<gQKV, 256>>>(px,
                                 wq + oD, bq + l * DMODEL,
                                 wk + oD, bk + l * DMODEL,
                                 wv + oD, bv + l * DMODEL,
                                 pq, pk, pv);

        attn_kernel<<<gA, 64>>>(mask);

        sgemm_bias<0><<<gD, 256>>>(patt, wo + oD, bo + l * DMODEL, ptmp, TOK, DMODEL, DMODEL);
        add_ln_kernel<<<TOK, 256>>>(ptmp, g1 + l * DMODEL, bb1 + l * DMODEL);

        sgemm_bias<1><<<gF, 256>>>(px, w1 + oF, b1 + l * FFDIM, pff, TOK, FFDIM, DMODEL);
        sgemm_bias<0><<<gD, 256>>>(pff, w2 + oF, b2 + l * DMODEL, ptmp, TOK, DMODEL, FFDIM);
        add_ln_kernel<<<TOK, 256>>>(ptmp, g2 + l * DMODEL, bb2 + l * DMODEL);
    }

    cls_kernel<<<1, 128>>>(cw, cb, out);
}

// round 4
// speedup vs baseline: 1.3044x; 1.3044x over previous
#include <cuda_runtime.h>
#include <cuda_bf16.h>
#include <math.h>
#include <stdint.h>

// Problem constants
#define BATCH 8
#define SEQL  1024
#define TOK   (BATCH*SEQL)     // 8192
#define DMODEL 768
#define NHEAD 12
#define DKHEAD 64
#define FFDIM 3072
#define NLAYER 6
#define NCLS  10

typedef __nv_bfloat16 bf16;

// ----------------------------------------------------------------------------
// Scratch (device globals — no runtime allocation allowed)
// ----------------------------------------------------------------------------
__device__ float g_x  [TOK * DMODEL];    // residual stream (fp32)
__device__ float g_q  [TOK * DMODEL];
__device__ float g_k  [TOK * DMODEL];
__device__ float g_v  [TOK * DMODEL];
__device__ float g_tmp[TOK * DMODEL];    // projection outputs pre-residual

__device__ bf16 g_xh [TOK * DMODEL];     // split residual (A operand)
__device__ bf16 g_xl [TOK * DMODEL];
__device__ bf16 g_ah [TOK * DMODEL];     // split attention output
__device__ bf16 g_al [TOK * DMODEL];
__device__ bf16 g_fh [TOK * FFDIM];      // split FFN hidden (post-ReLU)
__device__ bf16 g_fl [TOK * FFDIM];

// split weights (all layers contiguous)
__device__ bf16 g_wqh[NLAYER*DMODEL*DMODEL];  __device__ bf16 g_wql[NLAYER*DMODEL*DMODEL];
__device__ bf16 g_wkh[NLAYER*DMODEL*DMODEL];  __device__ bf16 g_wkl[NLAYER*DMODEL*DMODEL];
__device__ bf16 g_wvh[NLAYER*DMODEL*DMODEL];  __device__ bf16 g_wvl[NLAYER*DMODEL*DMODEL];
__device__ bf16 g_woh[NLAYER*DMODEL*DMODEL];  __device__ bf16 g_wol[NLAYER*DMODEL*DMODEL];
__device__ bf16 g_w1h[NLAYER*DMODEL*FFDIM];   __device__ bf16 g_w1l[NLAYER*DMODEL*FFDIM];
__device__ bf16 g_w2h[NLAYER*DMODEL*FFDIM];   __device__ bf16 g_w2l[NLAYER*DMODEL*FFDIM];

// ----------------------------------------------------------------------------
// MMA / ldmatrix helpers (base sm_103-compatible PTX; no tcgen05)
// ----------------------------------------------------------------------------
__device__ __forceinline__ uint32_t smem_to_u32(const void* p) {
    uint32_t a;
    asm("{ .reg .u64 t; cvta.to.shared.u64 t, %1; cvt.u32.u64 %0, t; }" : "=r"(a) : "l"(p));
    return a;
}
__device__ __forceinline__ void ldsm4(uint32_t* r, uint32_t a) {
    asm volatile("ldmatrix.sync.aligned.m8n8.x4.shared.b16 {%0,%1,%2,%3}, [%4];"
                 : "=r"(r[0]), "=r"(r[1]), "=r"(r[2]), "=r"(r[3]) : "r"(a));
}
__device__ __forceinline__ void ldsm4t(uint32_t* r, uint32_t a) {
    asm volatile("ldmatrix.sync.aligned.m8n8.x4.trans.shared.b16 {%0,%1,%2,%3}, [%4];"
                 : "=r"(r[0]), "=r"(r[1]), "=r"(r[2]), "=r"(r[3]) : "r"(a));
}
__device__ __forceinline__ void mma16816(float* d, const uint32_t* a, const uint32_t* b) {
    asm volatile("mma.sync.aligned.m16n8k16.row.col.f32.bf16.bf16.f32 "
                 "{%0,%1,%2,%3}, {%4,%5,%6,%7}, {%8,%9}, {%0,%1,%2,%3};"
                 : "+f"(d[0]), "+f"(d[1]), "+f"(d[2]), "+f"(d[3])
                 : "r"(a[0]), "r"(a[1]), "r"(a[2]), "r"(a[3]), "r"(b[0]), "r"(b[1]));
}

// ----------------------------------------------------------------------------
// Split helpers
// ----------------------------------------------------------------------------
__device__ __forceinline__ void split2_store(bf16* hi, bf16* lo, size_t idx, float v0, float v1) {
    bf16 h0 = __float2bfloat16(v0), h1 = __float2bfloat16(v1);
    float l0 = v0 - __bfloat162float(h0), l1 = v1 - __bfloat162float(h1);
    *(__nv_bfloat162*)(hi + idx) = __halves2bfloat162(h0, h1);
    *(__nv_bfloat162*)(lo + idx) = __halves2bfloat162(__float2bfloat16(l0), __float2bfloat16(l1));
}

__global__ void __launch_bounds__(256) split_kernel(const float* __restrict__ src,
                                                    bf16* __restrict__ hi, bf16* __restrict__ lo,
                                                    int n)
{
    int i = (blockIdx.x * 256 + threadIdx.x) * 4;
    if (i >= n) return;
    float4 v = *(const float4*)(src + i);
    split2_store(hi, lo, i, v.x, v.y);
    split2_store(hi, lo, i + 2, v.z, v.w);
}

// ----------------------------------------------------------------------------
// Embedding + sinusoidal PE  (writes fp32 x and bf16 hi/lo split)
// ----------------------------------------------------------------------------
__global__ void __launch_bounds__(256) embed_kernel(const int* __restrict__ ids,
                                                    const float* __restrict__ emb)
{
    int t = blockIdx.x;
    int pos = t & (SEQL - 1);
    const float* e = emb + (size_t)ids[t] * DMODEL;
    size_t base = (size_t)t * DMODEL;
    const float klog = -9.210340371976184f / (float)DMODEL;
    for (int p = threadIdx.x; p < DMODEL / 2; p += 256) {
        int d0 = 2 * p;
        float freq = expf((float)d0 * klog);
        float ang = (float)pos * freq;
        float v0 = e[d0] + sinf(ang);
        float v1 = e[d0 + 1] + cosf(ang);
        g_x[base + d0] = v0;
        g_x[base + d0 + 1] = v1;
        split2_store(g_xh, g_xl, base + d0, v0, v1);
    }
}

// ----------------------------------------------------------------------------
// Split-bf16 HMMA GEMM: C[M,Nfull] = A[M,K] @ W[K,Nfull] + bias
// A/W pre-split bf16 hi/lo; 3 accumulation passes (AhBh + AlBh + AhBl).
// CTA tile 128x128x32, 256 threads = 8 warps (4 m x 2 n), warp tile 32x64.
// ----------------------------------------------------------------------------
#define BK   32
#define APAD 40     // 32 + 8 bf16  (80 B rows -> ldmatrix bank-conflict-free)
#define BPAD 136    // 128 + 8 bf16 (272 B rows -> ldmatrix bank-conflict-free)

template<int RELU, int WF32, int WSPLIT>
__device__ __forceinline__ void gemm_body(
    const bf16* __restrict__ Ah_g, const bf16* __restrict__ Al_g,
    const bf16* __restrict__ Wh_g, const bf16* __restrict__ Wl_g,
    const float* __restrict__ bias,
    float* __restrict__ Cf, bf16* __restrict__ Ch, bf16* __restrict__ Cl,
    int Nfull, int K, int bx, int by)
{
    __shared__ bf16 sAh[128 * APAD];
    __shared__ bf16 sAl[128 * APAD];
    __shared__ bf16 sBh[BK * BPAD];
    __shared__ bf16 sBl[BK * BPAD];

    const int tid = threadIdx.x;
    const int wid = tid >> 5, lane = tid & 31;
    const int warp_m = wid >> 1;         // 0..3, 32 rows each
    const int warp_n = wid & 1;          // 0..1, 64 cols each
    const int m0 = by * 128, n0 = bx * 128;

    float acc[2][8][4];
#pragma unroll
    for (int mt = 0; mt < 2; mt++)
#pragma unroll
        for (int nt = 0; nt < 8; nt++)
#pragma unroll
            for (int r = 0; r < 4; r++) acc[mt][nt][r] = 0.f;

    for (int k0 = 0; k0 < K; k0 += BK) {
        // A tiles: 128 rows x 32 bf16 (4 x 16B segs/row); 512 slots, 2 iters
#pragma unroll
        for (int it = 0; it < 2; it++) {
            int slot = it * 256 + tid;
            int r = slot >> 2, sg = slot & 3;
            size_t gi = (size_t)(m0 + r) * K + k0 + sg * 8;
            *(uint4*)&sAh[r * APAD + sg * 8] = *(const uint4*)(Ah_g + gi);
            *(uint4*)&sAl[r * APAD + sg * 8] = *(const uint4*)(Al_g + gi);
        }
        // B tiles: 32 k-rows x 128 bf16 (16 x 16B segs/row); 512 slots, 2 iters
#pragma unroll
        for (int it = 0; it < 2; it++) {
            int slot = it * 256 + tid;
            int r = slot >> 4, sg = slot & 15;
            size_t gi = (size_t)(k0 + r) * Nfull + n0 + sg * 8;
            *(uint4*)&sBh[r * BPAD + sg * 8] = *(const uint4*)(Wh_g + gi);
            *(uint4*)&sBl[r * BPAD + sg * 8] = *(const uint4*)(Wl_g + gi);
        }
        __syncthreads();

#pragma unroll
        for (int pass = 0; pass < 3; pass++) {
            const bf16* sA = (pass == 1) ? sAl : sAh;
            const bf16* sB = (pass == 2) ? sBl : sBh;
#pragma unroll
            for (int kk = 0; kk < BK; kk += 16) {
                uint32_t af[2][4];
#pragma unroll
                for (int mt = 0; mt < 2; mt++) {
                    int row = warp_m * 32 + mt * 16 + (lane & 15);
                    int col = kk + ((lane >> 4) << 3);
                    ldsm4(af[mt], smem_to_u32(&sA[row * APAD + col]));
                }
                uint32_t bfr[4][4];
#pragma unroll
                for (int p = 0; p < 4; p++) {
                    int krow = kk + (lane & 15);
                    int col = warp_n * 64 + p * 16 + ((lane >> 4) << 3);
                    ldsm4t(bfr[p], smem_to_u32(&sB[krow * BPAD + col]));
                }
#pragma unroll
                for (int mt = 0; mt < 2; mt++)
#pragma unroll
                    for (int nt = 0; nt < 8; nt++)
                        mma16816(acc[mt][nt], af[mt], &bfr[nt >> 1][(nt & 1) * 2]);
            }
        }
        __syncthreads();
    }

    // Epilogue: d0,d1 -> (row, col..col+1); d2,d3 -> (row+8, col..col+1)
    const int rb = m0 + warp_m * 32;
    const int cb0 = n0 + warp_n * 64;
#pragma unroll
    for (int mt = 0; mt < 2; mt++)
#pragma unroll
        for (int nt = 0; nt < 8; nt++)
#pragma unroll
            for (int hh = 0; hh < 2; hh++) {
                int row = rb + mt * 16 + (lane >> 2) + hh * 8;
                int col = cb0 + nt * 8 + (lane & 3) * 2;
                float v0 = acc[mt][nt][hh * 2 + 0] + bias[col];
                float v1 = acc[mt][nt][hh * 2 + 1] + bias[col + 1];
                if (RELU) { v0 = fmaxf(v0, 0.f); v1 = fmaxf(v1, 0.f); }
                size_t oi = (size_t)row * Nfull + col;
                if (WF32)   *(float2*)(Cf + oi) = make_float2(v0, v1);
                if (WSPLIT) split2_store(Ch, Cl, oi, v0, v1);
            }
}

template<int RELU, int WF32, int WSPLIT>
__global__ void __launch_bounds__(256) gemm_sb(
    const bf16* __restrict__ Ah_g, const bf16* __restrict__ Al_g,
    const bf16* __restrict__ Wh_g, const bf16* __restrict__ Wl_g,
    const float* __restrict__ bias,
    float* __restrict__ Cf, bf16* __restrict__ Ch, bf16* __restrict__ Cl,
    int Nfull, int K)
{
    gemm_body<RELU, WF32, WSPLIT>(Ah_g, Al_g, Wh_g, Wl_g, bias, Cf, Ch, Cl,
                                  Nfull, K, blockIdx.x, blockIdx.y);
}

// Fused QKV: blockIdx.z selects weight/output triple.
__global__ void __launch_bounds__(256) gemm_qkv(
    const bf16* __restrict__ Wqh, const bf16* __restrict__ Wql, const float* __restrict__ Bq,
    const bf16* __restrict__ Wkh, const bf16* __restrict__ Wkl, const float* __restrict__ Bk,
    const bf16* __restrict__ Wvh, const bf16* __restrict__ Wvl, const float* __restrict__ Bv)
{
    const bf16 *wh, *wl; const float* bias; float* C;
    if (blockIdx.z == 0)      { wh = Wqh; wl = Wql; bias = Bq; C = g_q; }
    else if (blockIdx.z == 1) { wh = Wkh; wl = Wkl; bias = Bk; C = g_k; }
    else                      { wh = Wvh; wl = Wvl; bias = Bv; C = g_v; }
    gemm_body<0, 1, 0>(g_xh, g_xl, wh, wl, bias, C, nullptr, nullptr,
                       DMODEL, DMODEL, blockIdx.x, blockIdx.y);
}

// ----------------------------------------------------------------------------
// Attention (flash-style, fp32): one block = (b,h, 64 q-rows); thread = one row.
// 4-way split QK accumulators. Writes bf16 hi/lo split output directly.
// ----------------------------------------------------------------------------
__global__ void __launch_bounds__(64) attn_kernel(const int* __restrict__ mask)
{
    const int b = blockIdx.x / NHEAD;
    const int h = blockIdx.x % NHEAD;
    const int l = blockIdx.y * 64 + threadIdx.x;

    float q[DKHEAD];
    const float* qp = g_q + ((size_t)(b * SEQL + l)) * DMODEL + h * DKHEAD;
#pragma unroll
    for (int i = 0; i < DKHEAD; i++) q[i] = qp[i] * 0.125f;

    float o[DKHEAD];
#pragma unroll
    for (int i = 0; i < DKHEAD; i++) o[i] = 0.f;
    float m = -1e30f, ssum = 0.f;

    __shared__ float Ks[64][DKHEAD];
    __shared__ float Vs[64][DKHEAD];
    __shared__ float neg[64];

    for (int kt = 0; kt < SEQL / 64; kt++) {
        __syncthreads();
        int krow = kt * 64 + threadIdx.x;
        const float* kp = g_k + ((size_t)(b * SEQL + krow)) * DMODEL + h * DKHEAD;
        const float* vp = g_v + ((size_t)(b * SEQL + krow)) * DMODEL + h * DKHEAD;
#pragma unroll
        for (int i = 0; i < DKHEAD / 4; i++) {
            ((float4*)Ks[threadIdx.x])[i] = ((const float4*)kp)[i];
            ((float4*)Vs[threadIdx.x])[i] = ((const float4*)vp)[i];
        }
        neg[threadIdx.x] = (mask[b * SEQL + krow] == 0) ? -1e9f : 0.f;
        __syncthreads();

#pragma unroll
        for (int c = 0; c < 8; c++) {
            float s[8];
            float cmax = -1e30f;
#pragma unroll
            for (int j = 0; j < 8; j++) {
                int jj = c * 8 + j;
                float a0 = 0.f, a1 = 0.f, a2 = 0.f, a3 = 0.f;
#pragma unroll
                for (int i = 0; i < DKHEAD; i += 4) {
                    float4 kv = *(const float4*)&Ks[jj][i];
                    a0 = fmaf(q[i], kv.x, a0);
                    a1 = fmaf(q[i + 1], kv.y, a1);
                    a2 = fmaf(q[i + 2], kv.z, a2);
                    a3 = fmaf(q[i + 3], kv.w, a3);
                }
                s[j] = (a0 + a1) + (a2 + a3) + neg[jj];
                cmax = fmaxf(cmax, s[j]);
            }
            float nm = fmaxf(m, cmax);
            float corr = __expf(m - nm);
            m = nm;
            ssum *= corr;
#pragma unroll
            for (int i = 0; i < DKHEAD; i++) o[i] *= corr;
#pragma unroll
            for (int j = 0; j < 8; j++) {
                float p = __expf(s[j] - m);
                ssum += p;
#pragma unroll
                for (int i = 0; i < DKHEAD; i += 4) {
                    float4 vv = *(const float4*)&Vs[c * 8 + j][i];
                    o[i]     = fmaf(p, vv.x, o[i]);
                    o[i + 1] = fmaf(p, vv.y, o[i + 1]);
                    o[i + 2] = fmaf(p, vv.z, o[i + 2]);
                    o[i + 3] = fmaf(p, vv.w, o[i + 3]);
                }
            }
        }
    }

    float inv = 1.f / ssum;
    size_t obase = ((size_t)(b * SEQL + l)) * DMODEL + h * DKHEAD;
#pragma unroll
    for (int i = 0; i < DKHEAD; i += 2)
        split2_store(g_ah, g_al, obase + i, o[i] * inv, o[i + 1] * inv);
}

// ----------------------------------------------------------------------------
// Residual add + LayerNorm (in-place into g_x + bf16 split). One block/token.
// ----------------------------------------------------------------------------
__global__ void __launch_bounds__(256) add_ln_kernel(const float* __restrict__ y,
                                                     const float* __restrict__ gam,
                                                     const float* __restrict__ bet)
{
    int t = blockIdx.x;
    int tid = threadIdx.x;
    __shared__ float red[32];
    size_t base = (size_t)t * DMODEL;

    float2 z0, z1 = make_float2(0.f, 0.f);
    const bool has1 = (tid < DMODEL / 2 - 256);
    {
        float2 a = *(const float2*)(g_x + base + 2 * tid);
        float2 bb = *(const float2*)(y + base + 2 * tid);
        z0 = make_float2(a.x + bb.x, a.y + bb.y);
        if (has1) {
            float2 a1 = *(const float2*)(g_x + base + 2 * (tid + 256));
            float2 b1 = *(const float2*)(y + base + 2 * (tid + 256));
            z1 = make_float2(a1.x + b1.x, a1.y + b1.y);
        }
    }
    float s = z0.x + z0.y + z1.x + z1.y;
#pragma unroll
    for (int off = 16; off; off >>= 1) s += __shfl_xor_sync(0xffffffffu, s, off);
    if ((tid & 31) == 0) red[tid >> 5] = s;
    __syncthreads();
    if (tid < 32) {
        float v = (tid < 8) ? red[tid] : 0.f;
#pragma unroll
        for (int off = 4; off; off >>= 1) v += __shfl_xor_sync(0xffffffffu, v, off);
        if (tid == 0) red[0] = v;
    }
    __syncthreads();
    float mu = red[0] * (1.f / DMODEL);
    __syncthreads();

    float sq = 0.f;
    { float d0 = z0.x - mu, d1 = z0.y - mu; sq = fmaf(d0, d0, fmaf(d1, d1, sq)); }
    if (has1) { float d0 = z1.x - mu, d1 = z1.y - mu; sq = fmaf(d0, d0, fmaf(d1, d1, sq)); }
#pragma unroll
    for (int off = 16; off; off >>= 1) sq += __shfl_xor_sync(0xffffffffu, sq, off);
    if ((tid & 31) == 0) red[tid >> 5] = sq;
    __syncthreads();
    if (tid < 32) {
        float v = (tid < 8) ? red[tid] : 0.f;
#pragma unroll
        for (int off = 4; off; off >>= 1) v += __shfl_xor_sync(0xffffffffu, v, off);
        if (tid == 0) red[0] = v;
    }
    __syncthreads();
    float rstd = rsqrtf(red[0] * (1.f / DMODEL) + 1e-5f);

    {
        int d = 2 * tid;
        float n0 = (z0.x - mu) * rstd * gam[d] + bet[d];
        float n1 = (z0.y - mu) * rstd * gam[d + 1] + bet[d + 1];
        *(float2*)(g_x + base + d) = make_float2(n0, n1);
        split2_store(g_xh, g_xl, base + d, n0, n1);
    }
    if (has1) {
        int d = 2 * (tid + 256);
        float n0 = (z1.x - mu) * rstd * gam[d] + bet[d];
        float n1 = (z1.y - mu) * rstd * gam[d + 1] + bet[d + 1];
        *(float2*)(g_x + base + d) = make_float2(n0, n1);
        split2_store(g_xh, g_xl, base + d, n0, n1);
    }
}

// ----------------------------------------------------------------------------
// Classifier: out[b,c] = x[b, token 0, :] @ cls_w + cls_b
// ----------------------------------------------------------------------------
__global__ void cls_kernel(const float* __restrict__ w,
                           const float* __restrict__ cb,
                           float* __restrict__ out)
{
    int t = threadIdx.x;
    if (t >= BATCH * NCLS) return;
    int b = t / NCLS, c = t % NCLS;
    const float* xp = g_x + (size_t)b * SEQL * DMODEL;
    float s = cb[c];
    for (int d = 0; d < DMODEL; d++) s = fmaf(xp[d], w[d * NCLS + c], s);
    out[t] = s;
}

// ----------------------------------------------------------------------------
// Launch
// ----------------------------------------------------------------------------
extern "C" void kernel_launch(void* const* d_in, const int* in_sizes, int n_in,
                              void* d_out, int out_size)
{
    (void)in_sizes; (void)n_in; (void)out_size;
    const int*   ids  = (const int*)d_in[0];
    const int*   mask = (const int*)d_in[1];
    const float* emb  = (const float*)d_in[2];
    const float* wq = (const float*)d_in[3],  *bq = (const float*)d_in[4];
    const float* wk = (const float*)d_in[5],  *bk = (const float*)d_in[6];
    const float* wv = (const float*)d_in[7],  *bv = (const float*)d_in[8];
    const float* wo = (const float*)d_in[9],  *bo = (const float*)d_in[10];
    const float* g1 = (const float*)d_in[11], *bb1 = (const float*)d_in[12];
    const float* w1 = (const float*)d_in[13], *b1 = (const float*)d_in[14];
    const float* w2 = (const float*)d_in[15], *b2 = (const float*)d_in[16];
    const float* g2 = (const float*)d_in[17], *bb2 = (const float*)d_in[18];
    const float* cw = (const float*)d_in[19], *cb = (const float*)d_in[20];
    float* out = (float*)d_out;

    bf16 *wqh, *wql, *wkh, *wkl, *wvh, *wvl, *woh, *wol, *w1h, *w1l, *w2h, *w2l;
    { void* p;
      cudaGetSymbolAddress(&p, g_wqh); wqh = (bf16*)p; cudaGetSymbolAddress(&p, g_wql); wql = (bf16*)p;
      cudaGetSymbolAddress(&p, g_wkh); wkh = (bf16*)p; cudaGetSymbolAddress(&p, g_wkl); wkl = (bf16*)p;
      cudaGetSymbolAddress(&p, g_wvh); wvh = (bf16*)p; cudaGetSymbolAddress(&p, g_wvl); wvl = (bf16*)p;
      cudaGetSymbolAddress(&p, g_woh); woh = (bf16*)p; cudaGetSymbolAddress(&p, g_wol); wol = (bf16*)p;
      cudaGetSymbolAddress(&p, g_w1h); w1h = (bf16*)p; cudaGetSymbolAddress(&p, g_w1l); w1l = (bf16*)p;
      cudaGetSymbolAddress(&p, g_w2h); w2h = (bf16*)p; cudaGetSymbolAddress(&p, g_w2l); w2l = (bf16*)p;
    }
    bf16 *xh, *xl, *ah, *al, *fh, *fl;
    { void* p;
      cudaGetSymbolAddress(&p, g_xh); xh = (bf16*)p; cudaGetSymbolAddress(&p, g_xl); xl = (bf16*)p;
      cudaGetSymbolAddress(&p, g_ah); ah = (bf16*)p; cudaGetSymbolAddress(&p, g_al); al = (bf16*)p;
      cudaGetSymbolAddress(&p, g_fh); fh = (bf16*)p; cudaGetSymbolAddress(&p, g_fl); fl = (bf16*)p;
    }
    float *ptmp;
    { void* p; cudaGetSymbolAddress(&p, g_tmp); ptmp = (float*)p; }

    const int nDD = NLAYER * DMODEL * DMODEL;   // 3,538,944
    const int nDF = NLAYER * DMODEL * FFDIM;    // 14,155,776
    const int tb = 256;
    split_kernel<<<nDD / 4 / tb, tb>>>(wq, wqh, wql, nDD);
    split_kernel<<<nDD / 4 / tb, tb>>>(wk, wkh, wkl, nDD);
    split_kernel<<<nDD / 4 / tb, tb>>>(wv, wvh, wvl, nDD);
    split_kernel<<<nDD / 4 / tb, tb>>>(wo, woh, wol, nDD);
    split_kernel<<<nDF / 4 / tb, tb>>>(w1, w1h, w1l, nDF);
    split_kernel<<<nDF / 4 / tb, tb>>>(w2, w2h, w2l, nDF);

    embed_kernel<<<TOK, 256>>>(ids, emb);

    dim3 gD(DMODEL / 128, TOK / 128);        // (6, 64)
    dim3 gQKV(DMODEL / 128, TOK / 128, 3);   // (6, 64, 3)
    dim3 gF(FFDIM / 128, TOK / 128);         // (24, 64)
    dim3 gA(BATCH * NHEAD, SEQL / 64);       // (96, 16)

    for (int l = 0; l < NLAYER; l++) {
        size_t oD = (size_t)l * DMODEL * DMODEL;
        size_t oF = (size_t)l * DMODEL * FFDIM;

        gemm_qkv<<<gQKV, 256>>>(wqh + oD, wql + oD, bq + l * DMODEL,
                                wkh + oD, wkl + oD, bk + l * DMODEL,
                                wvh + oD, wvl + oD, bv + l * DMODEL);

        attn_kernel<<<gA, 64>>>(mask);

        gemm_sb<0,1,0><<<gD, 256>>>(ah, al, woh + oD, wol + oD, bo + l * DMODEL,
                                    ptmp, nullptr, nullptr, DMODEL, DMODEL);
        add_ln_kernel<<<TOK, 256>>>(ptmp, g1 + l * DMODEL, bb1 + l * DMODEL);

        gemm_sb<1,0,1><<<gF, 256>>>(xh, xl, w1h + oF, w1l + oF, b1 + l * FFDIM,
                                    nullptr, fh, fl, FFDIM, DMODEL);
        gemm_sb<0,1,0><<<gD, 256>>>(fh, fl, w2h + oF, w2l + oF, b2 + l * DMODEL,
                                    ptmp, nullptr, nullptr, DMODEL, FFDIM);
        add_ln_kernel<<<TOK, 256>>>(ptmp, g2 + l * DMODEL, bb2 + l * DMODEL);
    }

    cls_kernel<<<1, 128>>>(cw, cb, out);
}

// round 5
// speedup vs baseline: 2.6005x; 1.9937x over previous
#include <cuda_runtime.h>
#include <cuda_bf16.h>
#include <math.h>
#include <stdint.h>

// Problem constants
#define BATCH 8
#define SEQL  1024
#define TOK   (BATCH*SEQL)     // 8192
#define DMODEL 768
#define NHEAD 12
#define DKHEAD 64
#define FFDIM 3072
#define NLAYER 6
#define NCLS  10

typedef __nv_bfloat16 bf16;

// ----------------------------------------------------------------------------
// Scratch (device globals — no runtime allocation allowed)
// ----------------------------------------------------------------------------
__device__ float g_x  [TOK * DMODEL];    // residual stream (fp32)
__device__ float g_tmp[TOK * DMODEL];    // projection outputs pre-residual

__device__ bf16 g_xh [TOK * DMODEL];     // split residual (A operand)
__device__ bf16 g_xl [TOK * DMODEL];
__device__ bf16 g_ah [TOK * DMODEL];     // split attention output
__device__ bf16 g_al [TOK * DMODEL];
__device__ bf16 g_fh [TOK * FFDIM];      // split FFN hidden (post-ReLU)
__device__ bf16 g_fl [TOK * FFDIM];

// split Q/K/V (Q pre-scaled by 1/8)
__device__ bf16 g_qh [TOK * DMODEL];  __device__ bf16 g_ql [TOK * DMODEL];
__device__ bf16 g_kh [TOK * DMODEL];  __device__ bf16 g_kl [TOK * DMODEL];
__device__ bf16 g_vh [TOK * DMODEL];  __device__ bf16 g_vl [TOK * DMODEL];

// split weights (all layers contiguous)
__device__ bf16 g_wqh[NLAYER*DMODEL*DMODEL];  __device__ bf16 g_wql[NLAYER*DMODEL*DMODEL];
__device__ bf16 g_wkh[NLAYER*DMODEL*DMODEL];  __device__ bf16 g_wkl[NLAYER*DMODEL*DMODEL];
__device__ bf16 g_wvh[NLAYER*DMODEL*DMODEL];  __device__ bf16 g_wvl[NLAYER*DMODEL*DMODEL];
__device__ bf16 g_woh[NLAYER*DMODEL*DMODEL];  __device__ bf16 g_wol[NLAYER*DMODEL*DMODEL];
__device__ bf16 g_w1h[NLAYER*DMODEL*FFDIM];   __device__ bf16 g_w1l[NLAYER*DMODEL*FFDIM];
__device__ bf16 g_w2h[NLAYER*DMODEL*FFDIM];   __device__ bf16 g_w2l[NLAYER*DMODEL*FFDIM];

// ----------------------------------------------------------------------------
// MMA / ldmatrix helpers (base sm_103-compatible PTX; no tcgen05)
// ----------------------------------------------------------------------------
__device__ __forceinline__ uint32_t smem_to_u32(const void* p) {
    uint32_t a;
    asm("{ .reg .u64 t; cvta.to.shared.u64 t, %1; cvt.u32.u64 %0, t; }" : "=r"(a) : "l"(p));
    return a;
}
__device__ __forceinline__ void ldsm4(uint32_t* r, uint32_t a) {
    asm volatile("ldmatrix.sync.aligned.m8n8.x4.shared.b16 {%0,%1,%2,%3}, [%4];"
                 : "=r"(r[0]), "=r"(r[1]), "=r"(r[2]), "=r"(r[3]) : "r"(a));
}
__device__ __forceinline__ void ldsm4t(uint32_t* r, uint32_t a) {
    asm volatile("ldmatrix.sync.aligned.m8n8.x4.trans.shared.b16 {%0,%1,%2,%3}, [%4];"
                 : "=r"(r[0]), "=r"(r[1]), "=r"(r[2]), "=r"(r[3]) : "r"(a));
}
__device__ __forceinline__ void mma16816(float* d, const uint32_t* a, const uint32_t* b) {
    asm volatile("mma.sync.aligned.m16n8k16.row.col.f32.bf16.bf16.f32 "
                 "{%0,%1,%2,%3}, {%4,%5,%6,%7}, {%8,%9}, {%0,%1,%2,%3};"
                 : "+f"(d[0]), "+f"(d[1]), "+f"(d[2]), "+f"(d[3])
                 : "r"(a[0]), "r"(a[1]), "r"(a[2]), "r"(a[3]), "r"(b[0]), "r"(b[1]));
}

// ----------------------------------------------------------------------------
// Split helpers
// ----------------------------------------------------------------------------
__device__ __forceinline__ void split2_store(bf16* hi, bf16* lo, size_t idx, float v0, float v1) {
    bf16 h0 = __float2bfloat16(v0), h1 = __float2bfloat16(v1);
    float l0 = v0 - __bfloat162float(h0), l1 = v1 - __bfloat162float(h1);
    *(__nv_bfloat162*)(hi + idx) = __halves2bfloat162(h0, h1);
    *(__nv_bfloat162*)(lo + idx) = __halves2bfloat162(__float2bfloat16(l0), __float2bfloat16(l1));
}
__device__ __forceinline__ void splitpack(float a, float b, uint32_t& hi, uint32_t& lo) {
    bf16 ha = __float2bfloat16(a), hb = __float2bfloat16(b);
    float la = a - __bfloat162float(ha), lb = b - __bfloat162float(hb);
    __nv_bfloat162 hv = __halves2bfloat162(ha, hb);
    __nv_bfloat162 lv = __halves2bfloat162(__float2bfloat16(la), __float2bfloat16(lb));
    hi = *(uint32_t*)&hv;
    lo = *(uint32_t*)&lv;
}

__global__ void __launch_bounds__(256) split_kernel(const float* __restrict__ src,
                                                    bf16* __restrict__ hi, bf16* __restrict__ lo,
                                                    int n)
{
    int i = (blockIdx.x * 256 + threadIdx.x) * 4;
    if (i >= n) return;
    float4 v = *(const float4*)(src + i);
    split2_store(hi, lo, i, v.x, v.y);
    split2_store(hi, lo, i + 2, v.z, v.w);
}

// ----------------------------------------------------------------------------
// Embedding + sinusoidal PE  (writes fp32 x and bf16 hi/lo split)
// ----------------------------------------------------------------------------
__global__ void __launch_bounds__(256) embed_kernel(const int* __restrict__ ids,
                                                    const float* __restrict__ emb)
{
    int t = blockIdx.x;
    int pos = t & (SEQL - 1);
    const float* e = emb + (size_t)ids[t] * DMODEL;
    size_t base = (size_t)t * DMODEL;
    const float klog = -9.210340371976184f / (float)DMODEL;
    for (int p = threadIdx.x; p < DMODEL / 2; p += 256) {
        int d0 = 2 * p;
        float freq = expf((float)d0 * klog);
        float ang = (float)pos * freq;
        float v0 = e[d0] + sinf(ang);
        float v1 = e[d0 + 1] + cosf(ang);
        g_x[base + d0] = v0;
        g_x[base + d0 + 1] = v1;
        split2_store(g_xh, g_xl, base + d0, v0, v1);
    }
}

// ----------------------------------------------------------------------------
// Split-bf16 HMMA GEMM: C[M,Nfull] = A[M,K] @ W[K,Nfull] + bias
// CTA tile 128x128x32, 256 threads = 8 warps (4m x 2n), warp tile 32x64.
// ----------------------------------------------------------------------------
#define BK   32
#define APAD 40
#define BPAD 136

template<int RELU, int WF32, int WSPLIT>
__device__ __forceinline__ void gemm_body(
    const bf16* __restrict__ Ah_g, const bf16* __restrict__ Al_g,
    const bf16* __restrict__ Wh_g, const bf16* __restrict__ Wl_g,
    const float* __restrict__ bias,
    float* __restrict__ Cf, bf16* __restrict__ Ch, bf16* __restrict__ Cl,
    int Nfull, int K, int bx, int by, float oscale)
{
    __shared__ bf16 sAh[128 * APAD];
    __shared__ bf16 sAl[128 * APAD];
    __shared__ bf16 sBh[BK * BPAD];
    __shared__ bf16 sBl[BK * BPAD];

    const int tid = threadIdx.x;
    const int wid = tid >> 5, lane = tid & 31;
    const int warp_m = wid >> 1;
    const int warp_n = wid & 1;
    const int m0 = by * 128, n0 = bx * 128;

    float acc[2][8][4];
#pragma unroll
    for (int mt = 0; mt < 2; mt++)
#pragma unroll
        for (int nt = 0; nt < 8; nt++)
#pragma unroll
            for (int r = 0; r < 4; r++) acc[mt][nt][r] = 0.f;

    for (int k0 = 0; k0 < K; k0 += BK) {
#pragma unroll
        for (int it = 0; it < 2; it++) {
            int slot = it * 256 + tid;
            int r = slot >> 2, sg = slot & 3;
            size_t gi = (size_t)(m0 + r) * K + k0 + sg * 8;
            *(uint4*)&sAh[r * APAD + sg * 8] = *(const uint4*)(Ah_g + gi);
            *(uint4*)&sAl[r * APAD + sg * 8] = *(const uint4*)(Al_g + gi);
        }
#pragma unroll
        for (int it = 0; it < 2; it++) {
            int slot = it * 256 + tid;
            int r = slot >> 4, sg = slot & 15;
            size_t gi = (size_t)(k0 + r) * Nfull + n0 + sg * 8;
            *(uint4*)&sBh[r * BPAD + sg * 8] = *(const uint4*)(Wh_g + gi);
            *(uint4*)&sBl[r * BPAD + sg * 8] = *(const uint4*)(Wl_g + gi);
        }
        __syncthreads();

#pragma unroll
        for (int pass = 0; pass < 3; pass++) {
            const bf16* sA = (pass == 1) ? sAl : sAh;
            const bf16* sB = (pass == 2) ? sBl : sBh;
#pragma unroll
            for (int kk = 0; kk < BK; kk += 16) {
                uint32_t af[2][4];
#pragma unroll
                for (int mt = 0; mt < 2; mt++) {
                    int row = warp_m * 32 + mt * 16 + (lane & 15);
                    int col = kk + ((lane >> 4) << 3);
                    ldsm4(af[mt], smem_to_u32(&sA[row * APAD + col]));
                }
                uint32_t bfr[4][4];
#pragma unroll
                for (int p = 0; p < 4; p++) {
                    int krow = kk + (lane & 15);
                    int col = warp_n * 64 + p * 16 + ((lane >> 4) << 3);
                    ldsm4t(bfr[p], smem_to_u32(&sB[krow * BPAD + col]));
                }
#pragma unroll
                for (int mt = 0; mt < 2; mt++)
#pragma unroll
                    for (int nt = 0; nt < 8; nt++)
                        mma16816(acc[mt][nt], af[mt], &bfr[nt >> 1][(nt & 1) * 2]);
            }
        }
        __syncthreads();
    }

    const int rb = m0 + warp_m * 32;
    const int cb0 = n0 + warp_n * 64;
#pragma unroll
    for (int mt = 0; mt < 2; mt++)
#pragma unroll
        for (int nt = 0; nt < 8; nt++)
#pragma unroll
            for (int hh = 0; hh < 2; hh++) {
                int row = rb + mt * 16 + (lane >> 2) + hh * 8;
                int col = cb0 + nt * 8 + (lane & 3) * 2;
                float v0 = acc[mt][nt][hh * 2 + 0] + bias[col];
                float v1 = acc[mt][nt][hh * 2 + 1] + bias[col + 1];
                if (RELU) { v0 = fmaxf(v0, 0.f); v1 = fmaxf(v1, 0.f); }
                v0 *= oscale; v1 *= oscale;
                size_t oi = (size_t)row * Nfull + col;
                if (WF32)   *(float2*)(Cf + oi) = make_float2(v0, v1);
                if (WSPLIT) split2_store(Ch, Cl, oi, v0, v1);
            }
}

template<int RELU, int WF32, int WSPLIT>
__global__ void __launch_bounds__(256) gemm_sb(
    const bf16* __restrict__ Ah_g, const bf16* __restrict__ Al_g,
    const bf16* __restrict__ Wh_g, const bf16* __restrict__ Wl_g,
    const float* __restrict__ bias,
    float* __restrict__ Cf, bf16* __restrict__ Ch, bf16* __restrict__ Cl,
    int Nfull, int K)
{
    gemm_body<RELU, WF32, WSPLIT>(Ah_g, Al_g, Wh_g, Wl_g, bias, Cf, Ch, Cl,
                                  Nfull, K, blockIdx.x, blockIdx.y, 1.0f);
}

// Fused QKV: blockIdx.z selects weight/output triple; writes split bf16.
// Q is scaled by 1/8 (attention scale) at the epilogue.
__global__ void __launch_bounds__(256) gemm_qkv(
    const bf16* __restrict__ Wqh, const bf16* __restrict__ Wql, const float* __restrict__ Bq,
    const bf16* __restrict__ Wkh, const bf16* __restrict__ Wkl, const float* __restrict__ Bk,
    const bf16* __restrict__ Wvh, const bf16* __restrict__ Wvl, const float* __restrict__ Bv)
{
    const bf16 *wh, *wl; const float* bias; bf16 *ch, *cl; float sc;
    if (blockIdx.z == 0)      { wh = Wqh; wl = Wql; bias = Bq; ch = g_qh; cl = g_ql; sc = 0.125f; }
    else if (blockIdx.z == 1) { wh = Wkh; wl = Wkl; bias = Bk; ch = g_kh; cl = g_kl; sc = 1.0f; }
    else                      { wh = Wvh; wl = Wvl; bias = Bv; ch = g_vh; cl = g_vl; sc = 1.0f; }
    gemm_body<0, 0, 1>(g_xh, g_xl, wh, wl, bias, nullptr, ch, cl,
                       DMODEL, DMODEL, blockIdx.x, blockIdx.y, sc);
}

// ----------------------------------------------------------------------------
// Tensor-core flash attention. Block = (b,h, 64 q-rows), 4 warps x 16 rows.
// S = Q.K^T split-bf16 3-pass; online softmax in C-frag layout; P split hi/lo
// in-register; P.V split 3-pass. K/V chunks of 64 keys staged in smem.
// ----------------------------------------------------------------------------
#define ATPAD 72   // 64+8 bf16 -> 144B rows, ldmatrix bank-conflict-free

__global__ void __launch_bounds__(128) attn_mma(const int* __restrict__ mask)
{
    const int bh = blockIdx.x;
    const int b = bh / NHEAD, h = bh % NHEAD;
    const int qt = blockIdx.y;
    const int tid = threadIdx.x, wid = tid >> 5, lane = tid & 31;
    const int c0 = (lane & 3) * 2;

    __shared__ bf16 sKh[64 * ATPAD], sKl[64 * ATPAD];
    __shared__ bf16 sVh[64 * ATPAD], sVl[64 * ATPAD];
    __shared__ float sneg[64];

    // Stage Q tile (64x64) through sKh/sKl, extract A-fragments.
    {
        size_t qbase = ((size_t)(b * SEQL + qt * 64)) * DMODEL + h * DKHEAD;
#pragma unroll
        for (int it = 0; it < 4; it++) {
            int slot = it * 128 + tid;         // 512 slots of 8 bf16
            int r = slot >> 3, c = (slot & 7) * 8;
            size_t gi = qbase + (size_t)r * DMODEL + c;
            *(uint4*)&sKh[r * ATPAD + c] = *(const uint4*)(g_qh + gi);
            *(uint4*)&sKl[r * ATPAD + c] = *(const uint4*)(g_ql + gi);
        }
    }
    __syncthreads();
    uint32_t qfh[4][4], qfl[4][4];
#pragma unroll
    for (int ks = 0; ks < 4; ks++) {
        int row = wid * 16 + (lane & 15);
        int col = ks * 16 + ((lane >> 4) << 3);
        ldsm4(qfh[ks], smem_to_u32(&sKh[row * ATPAD + col]));
        ldsm4(qfl[ks], smem_to_u32(&sKl[row * ATPAD + col]));
    }
    __syncthreads();

    float o[8][4];
#pragma unroll
    for (int nt = 0; nt < 8; nt++)
#pragma unroll
        for (int r = 0; r < 4; r++) o[nt][r] = 0.f;
    float m0 = -1e30f, m1 = -1e30f, sum0 = 0.f, sum1 = 0.f;

    for (int kt = 0; kt < SEQL / 64; kt++) {
        size_t kb = ((size_t)(b * SEQL + kt * 64)) * DMODEL + h * DKHEAD;
#pragma unroll
        for (int it = 0; it < 4; it++) {
            int slot = it * 128 + tid;
            int r = slot >> 3, c = (slot & 7) * 8;
            size_t gi = kb + (size_t)r * DMODEL + c;
            *(uint4*)&sKh[r * ATPAD + c] = *(const uint4*)(g_kh + gi);
            *(uint4*)&sKl[r * ATPAD + c] = *(const uint4*)(g_kl + gi);
            *(uint4*)&sVh[r * ATPAD + c] = *(const uint4*)(g_vh + gi);
            *(uint4*)&sVl[r * ATPAD + c] = *(const uint4*)(g_vl + gi);
        }
        if (tid < 64) sneg[tid] = (mask[b * SEQL + kt * 64 + tid] == 0) ? -1e9f : 0.f;
        __syncthreads();

        // ---- S = Q.K^T (3 passes fused per k-step) ----
        float S[8][4];
#pragma unroll
        for (int nt = 0; nt < 8; nt++)
#pragma unroll
            for (int r = 0; r < 4; r++) S[nt][r] = 0.f;
#pragma unroll
        for (int ks = 0; ks < 4; ks++) {
            uint32_t kbh[4][4], kbl[4][4];
#pragma unroll
            for (int g = 0; g < 4; g++) {
                int nrow = g * 16 + (lane & 7) + ((lane & 16) ? 8 : 0);
                int ncol = ks * 16 + ((lane & 8) ? 8 : 0);
                ldsm4(kbh[g], smem_to_u32(&sKh[nrow * ATPAD + ncol]));
                ldsm4(kbl[g], smem_to_u32(&sKl[nrow * ATPAD + ncol]));
            }
#pragma unroll
            for (int nt = 0; nt < 8; nt++) {
                const uint32_t* bh_ = &kbh[nt >> 1][(nt & 1) * 2];
                const uint32_t* bl_ = &kbl[nt >> 1][(nt & 1) * 2];
                mma16816(S[nt], qfh[ks], bh_);
                mma16816(S[nt], qfl[ks], bh_);
                mma16816(S[nt], qfh[ks], bl_);
            }
        }

        // ---- mask + online softmax ----
        float mx0 = -1e30f, mx1 = -1e30f;
#pragma unroll
        for (int nt = 0; nt < 8; nt++) {
            float n0 = sneg[nt * 8 + c0], n1 = sneg[nt * 8 + c0 + 1];
            S[nt][0] += n0; S[nt][1] += n1; S[nt][2] += n0; S[nt][3] += n1;
            mx0 = fmaxf(mx0, fmaxf(S[nt][0], S[nt][1]));
            mx1 = fmaxf(mx1, fmaxf(S[nt][2], S[nt][3]));
        }
        mx0 = fmaxf(mx0, __shfl_xor_sync(0xffffffffu, mx0, 1));
        mx0 = fmaxf(mx0, __shfl_xor_sync(0xffffffffu, mx0, 2));
        mx1 = fmaxf(mx1, __shfl_xor_sync(0xffffffffu, mx1, 1));
        mx1 = fmaxf(mx1, __shfl_xor_sync(0xffffffffu, mx1, 2));
        float nm0 = fmaxf(m0, mx0), nm1 = fmaxf(m1, mx1);
        float cr0 = __expf(m0 - nm0), cr1 = __expf(m1 - nm1);
        m0 = nm0; m1 = nm1;
        sum0 *= cr0; sum1 *= cr1;
#pragma unroll
        for (int nt = 0; nt < 8; nt++) {
            o[nt][0] *= cr0; o[nt][1] *= cr0; o[nt][2] *= cr1; o[nt][3] *= cr1;
        }

        // ---- P (split hi/lo in-register) and P.V ----
        float ls0 = 0.f, ls1 = 0.f;
#pragma unroll
        for (int ks = 0; ks < 4; ks++) {
            const int j = 2 * ks, j1 = 2 * ks + 1;
            float p00 = __expf(S[j][0] - m0),  p01 = __expf(S[j][1] - m0);
            float p10 = __expf(S[j][2] - m1),  p11 = __expf(S[j][3] - m1);
            float r00 = __expf(S[j1][0] - m0), r01 = __expf(S[j1][1] - m0);
            float r10 = __expf(S[j1][2] - m1), r11 = __expf(S[j1][3] - m1);
            ls0 += p00 + p01 + r00 + r01;
            ls1 += p10 + p11 + r10 + r11;
            uint32_t ah[4], al[4];
            splitpack(p00, p01, ah[0], al[0]);
            splitpack(p10, p11, ah[1], al[1]);
            splitpack(r00, r01, ah[2], al[2]);
            splitpack(r10, r11, ah[3], al[3]);
            uint32_t vbh[4][4], vbl[4][4];
#pragma unroll
            for (int g = 0; g < 4; g++) {
                int vrow = ks * 16 + (lane & 15);
                int vcol = g * 16 + ((lane >> 4) << 3);
                ldsm4t(vbh[g], smem_to_u32(&sVh[vrow * ATPAD + vcol]));
                ldsm4t(vbl[g], smem_to_u32(&sVl[vrow * ATPAD + vcol]));
            }
#pragma unroll
            for (int nt = 0; nt < 8; nt++) {
                const uint32_t* bh_ = &vbh[nt >> 1][(nt & 1) * 2];
                const uint32_t* bl_ = &vbl[nt >> 1][(nt & 1) * 2];
                mma16816(o[nt], ah, bh_);
                mma16816(o[nt], al, bh_);
                mma16816(o[nt], ah, bl_);
            }
        }
        ls0 += __shfl_xor_sync(0xffffffffu, ls0, 1);
        ls0 += __shfl_xor_sync(0xffffffffu, ls0, 2);
        ls1 += __shfl_xor_sync(0xffffffffu, ls1, 1);
        ls1 += __shfl_xor_sync(0xffffffffu, ls1, 2);
        sum0 += ls0; sum1 += ls1;
        __syncthreads();
    }

    float inv0 = 1.f / sum0, inv1 = 1.f / sum1;
    int row0 = qt * 64 + wid * 16 + (lane >> 2);
    size_t ob0 = ((size_t)(b * SEQL + row0)) * DMODEL + h * DKHEAD;
    size_t ob1 = ob0 + (size_t)8 * DMODEL;
#pragma unroll
    for (int nt = 0; nt < 8; nt++) {
        int col = nt * 8 + c0;
        split2_store(g_ah, g_al, ob0 + col, o[nt][0] * inv0, o[nt][1] * inv0);
        split2_store(g_ah, g_al, ob1 + col, o[nt][2] * inv1, o[nt][3] * inv1);
    }
}

// ----------------------------------------------------------------------------
// Residual add + LayerNorm (in-place into g_x + bf16 split). One block/token.
// ----------------------------------------------------------------------------
__global__ void __launch_bounds__(256) add_ln_kernel(const float* __restrict__ y,
                                                     const float* __restrict__ gam,
                                                     const float* __restrict__ bet)
{
    int t = blockIdx.x;
    int tid = threadIdx.x;
    __shared__ float red[32];
    size_t base = (size_t)t * DMODEL;

    float2 z0, z1 = make_float2(0.f, 0.f);
    const bool has1 = (tid < DMODEL / 2 - 256);
    {
        float2 a = *(const float2*)(g_x + base + 2 * tid);
        float2 bb = *(const float2*)(y + base + 2 * tid);
        z0 = make_float2(a.x + bb.x, a.y + bb.y);
        if (has1) {
            float2 a1 = *(const float2*)(g_x + base + 2 * (tid + 256));
            float2 b1 = *(const float2*)(y + base + 2 * (tid + 256));
            z1 = make_float2(a1.x + b1.x, a1.y + b1.y);
        }
    }
    float s = z0.x + z0.y + z1.x + z1.y;
#pragma unroll
    for (int off = 16; off; off >>= 1) s += __shfl_xor_sync(0xffffffffu, s, off);
    if ((tid & 31) == 0) red[tid >> 5] = s;
    __syncthreads();
    if (tid < 32) {
        float v = (tid < 8) ? red[tid] : 0.f;
#pragma unroll
        for (int off = 4; off; off >>= 1) v += __shfl_xor_sync(0xffffffffu, v, off);
        if (tid == 0) red[0] = v;
    }
    __syncthreads();
    float mu = red[0] * (1.f / DMODEL);
    __syncthreads();

    float sq = 0.f;
    { float d0 = z0.x - mu, d1 = z0.y - mu; sq = fmaf(d0, d0, fmaf(d1, d1, sq)); }
    if (has1) { float d0 = z1.x - mu, d1 = z1.y - mu; sq = fmaf(d0, d0, fmaf(d1, d1, sq)); }
#pragma unroll
    for (int off = 16; off; off >>= 1) sq += __shfl_xor_sync(0xffffffffu, sq, off);
    if ((tid & 31) == 0) red[tid >> 5] = sq;
    __syncthreads();
    if (tid < 32) {
        float v = (tid < 8) ? red[tid] : 0.f;
#pragma unroll
        for (int off = 4; off; off >>= 1) v += __shfl_xor_sync(0xffffffffu, v, off);
        if (tid == 0) red[0] = v;
    }
    __syncthreads();
    float rstd = rsqrtf(red[0] * (1.f / DMODEL) + 1e-5f);

    {
        int d = 2 * tid;
        float n0 = (z0.x - mu) * rstd * gam[d] + bet[d];
        float n1 = (z0.y - mu) * rstd * gam[d + 1] + bet[d + 1];
        *(float2*)(g_x + base + d) = make_float2(n0, n1);
        split2_store(g_xh, g_xl, base + d, n0, n1);
    }
    if (has1) {
        int d = 2 * (tid + 256);
        float n0 = (z1.x - mu) * rstd * gam[d] + bet[d];
        float n1 = (z1.y - mu) * rstd * gam[d + 1] + bet[d + 1];
        *(float2*)(g_x + base + d) = make_float2(n0, n1);
        split2_store(g_xh, g_xl, base + d, n0, n1);
    }
}

// ----------------------------------------------------------------------------
// Classifier
// ----------------------------------------------------------------------------
__global__ void cls_kernel(const float* __restrict__ w,
                           const float* __restrict__ cb,
                           float* __restrict__ out)
{
    int t = threadIdx.x;
    if (t >= BATCH * NCLS) return;
    int b = t / NCLS, c = t % NCLS;
    const float* xp = g_x + (size_t)b * SEQL * DMODEL;
    float s = cb[c];
    for (int d = 0; d < DMODEL; d++) s = fmaf(xp[d], w[d * NCLS + c], s);
    out[t] = s;
}

// ----------------------------------------------------------------------------
// Launch
// ----------------------------------------------------------------------------
extern "C" void kernel_launch(void* const* d_in, const int* in_sizes, int n_in,
                              void* d_out, int out_size)
{
    (void)in_sizes; (void)n_in; (void)out_size;
    const int*   ids  = (const int*)d_in[0];
    const int*   mask = (const int*)d_in[1];
    const float* emb  = (const float*)d_in[2];
    const float* wq = (const float*)d_in[3],  *bq = (const float*)d_in[4];
    const float* wk = (const float*)d_in[5],  *bk = (const float*)d_in[6];
    const float* wv = (const float*)d_in[7],  *bv = (const float*)d_in[8];
    const float* wo = (const float*)d_in[9],  *bo = (const float*)d_in[10];
    const float* g1 = (const float*)d_in[11], *bb1 = (const float*)d_in[12];
    const float* w1 = (const float*)d_in[13], *b1 = (const float*)d_in[14];
    const float* w2 = (const float*)d_in[15], *b2 = (const float*)d_in[16];
    const float* g2 = (const float*)d_in[17], *bb2 = (const float*)d_in[18];
    const float* cw = (const float*)d_in[19], *cb = (const float*)d_in[20];
    float* out = (float*)d_out;

    bf16 *wqh, *wql, *wkh, *wkl, *wvh, *wvl, *woh, *wol, *w1h, *w1l, *w2h, *w2l;
    { void* p;
      cudaGetSymbolAddress(&p, g_wqh); wqh = (bf16*)p; cudaGetSymbolAddress(&p, g_wql); wql = (bf16*)p;
      cudaGetSymbolAddress(&p, g_wkh); wkh = (bf16*)p; cudaGetSymbolAddress(&p, g_wkl); wkl = (bf16*)p;
      cudaGetSymbolAddress(&p, g_wvh); wvh = (bf16*)p; cudaGetSymbolAddress(&p, g_wvl); wvl = (bf16*)p;
      cudaGetSymbolAddress(&p, g_woh); woh = (bf16*)p; cudaGetSymbolAddress(&p, g_wol); wol = (bf16*)p;
      cudaGetSymbolAddress(&p, g_w1h); w1h = (bf16*)p; cudaGetSymbolAddress(&p, g_w1l); w1l = (bf16*)p;
      cudaGetSymbolAddress(&p, g_w2h); w2h = (bf16*)p; cudaGetSymbolAddress(&p, g_w2l); w2l = (bf16*)p;
    }
    bf16 *xh, *xl, *ah, *al, *fh, *fl;
    { void* p;
      cudaGetSymbolAddress(&p, g_xh); xh = (bf16*)p; cudaGetSymbolAddress(&p, g_xl); xl = (bf16*)p;
      cudaGetSymbolAddress(&p, g_ah); ah = (bf16*)p; cudaGetSymbolAddress(&p, g_al); al = (bf16*)p;
      cudaGetSymbolAddress(&p, g_fh); fh = (bf16*)p; cudaGetSymbolAddress(&p, g_fl); fl = (bf16*)p;
    }
    float *ptmp;
    { void* p; cudaGetSymbolAddress(&p, g_tmp); ptmp = (float*)p; }

    const int nDD = NLAYER * DMODEL * DMODEL;
    const int nDF = NLAYER * DMODEL * FFDIM;
    const int tb = 256;

    dim3 gD(DMODEL / 128, TOK / 128);        // (6, 64)
    dim3 gQKV(DMODEL / 128, TOK / 128, 3);   // (6, 64, 3)
    dim3 gF(FFDIM / 128, TOK / 128);         // (24, 64)
    dim3 gA(BATCH * NHEAD, SEQL / 64);       // (96, 16)

    // Launch order chosen so ncu's "-s 5 -c 1" captures the layer-0 QKV GEMM.
    split_kernel<<<nDD / 4 / tb, tb>>>(wq, wqh, wql, nDD);   // 0
    split_kernel<<<nDD / 4 / tb, tb>>>(wk, wkh, wkl, nDD);   // 1
    split_kernel<<<nDD / 4 / tb, tb>>>(wv, wvh, wvl, nDD);   // 2
    embed_kernel<<<TOK, 256>>>(ids, emb);                    // 3
    split_kernel<<<nDD / 4 / tb, tb>>>(wo, woh, wol, nDD);   // 4

    for (int l = 0; l < NLAYER; l++) {
        size_t oD = (size_t)l * DMODEL * DMODEL;
        size_t oF = (size_t)l * DMODEL * FFDIM;

        gemm_qkv<<<gQKV, 256>>>(wqh + oD, wql + oD, bq + l * DMODEL,   // 5 for l=0
                                wkh + oD, wkl + oD, bk + l * DMODEL,
                                wvh + oD, wvl + oD, bv + l * DMODEL);

        attn_mma<<<gA, 128>>>(mask);

        if (l == 0) {
            split_kernel<<<nDF / 4 / tb, tb>>>(w1, w1h, w1l, nDF);
            split_kernel<<<nDF / 4 / tb, tb>>>(w2, w2h, w2l, nDF);
        }

        gemm_sb<0,1,0><<<gD, 256>>>(ah, al, woh + oD, wol + oD, bo + l * DMODEL,
                                    ptmp, nullptr, nullptr, DMODEL, DMODEL);
        add_ln_kernel<<<TOK, 256>>>(ptmp, g1 + l * DMODEL, bb1 + l * DMODEL);

        gemm_sb<1,0,1><<<gF, 256>>>(xh, xl, w1h + oF, w1l + oF, b1 + l * FFDIM,
                                    nullptr, fh, fl, FFDIM, DMODEL);
        gemm_sb<0,1,0><<<gD, 256>>>(fh, fl, w2h + oF, w2l + oF, b2 + l * DMODEL,
                                    ptmp, nullptr, nullptr, DMODEL, FFDIM);
        add_ln_kernel<<<TOK, 256>>>(ptmp, g2 + l * DMODEL, bb2 + l * DMODEL);
    }

    cls_kernel<<<1, 128>>>(cw, cb, out);
}

// round 6
// speedup vs baseline: 3.1246x; 1.2016x over previous
#include <cuda_runtime.h>
#include <cuda_bf16.h>
#include <math.h>
#include <stdint.h>

// Problem constants
#define BATCH 8
#define SEQL  1024
#define TOK   (BATCH*SEQL)     // 8192
#define DMODEL 768
#define NHEAD 12
#define DKHEAD 64
#define FFDIM 3072
#define NLAYER 6
#define NCLS  10

typedef __nv_bfloat16 bf16;

// ----------------------------------------------------------------------------
// Scratch (device globals — no runtime allocation allowed)
// ----------------------------------------------------------------------------
__device__ float g_x  [TOK * DMODEL];    // residual stream (fp32)
__device__ float g_tmp[TOK * DMODEL];    // projection outputs pre-residual

__device__ bf16 g_xh [TOK * DMODEL];     // split residual (A operand)
__device__ bf16 g_xl [TOK * DMODEL];
__device__ bf16 g_ah [TOK * DMODEL];     // split attention output
__device__ bf16 g_al [TOK * DMODEL];
__device__ bf16 g_fh [TOK * FFDIM];      // split FFN hidden (post-ReLU)
__device__ bf16 g_fl [TOK * FFDIM];

// split Q/K/V (Q pre-scaled by 1/8)
__device__ bf16 g_qh [TOK * DMODEL];  __device__ bf16 g_ql [TOK * DMODEL];
__device__ bf16 g_kh [TOK * DMODEL];  __device__ bf16 g_kl [TOK * DMODEL];
__device__ bf16 g_vh [TOK * DMODEL];  __device__ bf16 g_vl [TOK * DMODEL];

// split weights (all layers contiguous)
__device__ bf16 g_wqh[NLAYER*DMODEL*DMODEL];  __device__ bf16 g_wql[NLAYER*DMODEL*DMODEL];
__device__ bf16 g_wkh[NLAYER*DMODEL*DMODEL];  __device__ bf16 g_wkl[NLAYER*DMODEL*DMODEL];
__device__ bf16 g_wvh[NLAYER*DMODEL*DMODEL];  __device__ bf16 g_wvl[NLAYER*DMODEL*DMODEL];
__device__ bf16 g_woh[NLAYER*DMODEL*DMODEL];  __device__ bf16 g_wol[NLAYER*DMODEL*DMODEL];
__device__ bf16 g_w1h[NLAYER*DMODEL*FFDIM];   __device__ bf16 g_w1l[NLAYER*DMODEL*FFDIM];
__device__ bf16 g_w2h[NLAYER*DMODEL*FFDIM];   __device__ bf16 g_w2l[NLAYER*DMODEL*FFDIM];

// ----------------------------------------------------------------------------
// MMA / ldmatrix / cp.async helpers (base sm_103-compatible PTX)
// ----------------------------------------------------------------------------
__device__ __forceinline__ uint32_t smem_to_u32(const void* p) {
    uint32_t a;
    asm("{ .reg .u64 t; cvta.to.shared.u64 t, %1; cvt.u32.u64 %0, t; }" : "=r"(a) : "l"(p));
    return a;
}
__device__ __forceinline__ void ldsm4(uint32_t* r, uint32_t a) {
    asm volatile("ldmatrix.sync.aligned.m8n8.x4.shared.b16 {%0,%1,%2,%3}, [%4];"
                 : "=r"(r[0]), "=r"(r[1]), "=r"(r[2]), "=r"(r[3]) : "r"(a));
}
__device__ __forceinline__ void ldsm4t(uint32_t* r, uint32_t a) {
    asm volatile("ldmatrix.sync.aligned.m8n8.x4.trans.shared.b16 {%0,%1,%2,%3}, [%4];"
                 : "=r"(r[0]), "=r"(r[1]), "=r"(r[2]), "=r"(r[3]) : "r"(a));
}
__device__ __forceinline__ void mma16816(float* d, const uint32_t* a, const uint32_t* b) {
    asm volatile("mma.sync.aligned.m16n8k16.row.col.f32.bf16.bf16.f32 "
                 "{%0,%1,%2,%3}, {%4,%5,%6,%7}, {%8,%9}, {%0,%1,%2,%3};"
                 : "+f"(d[0]), "+f"(d[1]), "+f"(d[2]), "+f"(d[3])
                 : "r"(a[0]), "r"(a[1]), "r"(a[2]), "r"(a[3]), "r"(b[0]), "r"(b[1]));
}
__device__ __forceinline__ void cp16(uint32_t dst, const void* src) {
    asm volatile("cp.async.cg.shared.global [%0], [%1], 16;" :: "r"(dst), "l"(src));
}
__device__ __forceinline__ void cp_commit() {
    asm volatile("cp.async.commit_group;" ::: "memory");
}
template<int N>
__device__ __forceinline__ void cp_wait() {
    asm volatile("cp.async.wait_group %0;" :: "n"(N) : "memory");
}

// ----------------------------------------------------------------------------
// Split helpers
// ----------------------------------------------------------------------------
__device__ __forceinline__ void split2_store(bf16* hi, bf16* lo, size_t idx, float v0, float v1) {
    bf16 h0 = __float2bfloat16(v0), h1 = __float2bfloat16(v1);
    float l0 = v0 - __bfloat162float(h0), l1 = v1 - __bfloat162float(h1);
    *(__nv_bfloat162*)(hi + idx) = __halves2bfloat162(h0, h1);
    *(__nv_bfloat162*)(lo + idx) = __halves2bfloat162(__float2bfloat16(l0), __float2bfloat16(l1));
}
__device__ __forceinline__ void splitpack(float a, float b, uint32_t& hi, uint32_t& lo) {
    bf16 ha = __float2bfloat16(a), hb = __float2bfloat16(b);
    float la = a - __bfloat162float(ha), lb = b - __bfloat162float(hb);
    __nv_bfloat162 hv = __halves2bfloat162(ha, hb);
    __nv_bfloat162 lv = __halves2bfloat162(__float2bfloat16(la), __float2bfloat16(lb));
    hi = *(uint32_t*)&hv;
    lo = *(uint32_t*)&lv;
}

__global__ void __launch_bounds__(256) split_kernel(const float* __restrict__ src,
                                                    bf16* __restrict__ hi, bf16* __restrict__ lo,
                                                    int n)
{
    int i = (blockIdx.x * 256 + threadIdx.x) * 4;
    if (i >= n) return;
    float4 v = *(const float4*)(src + i);
    split2_store(hi, lo, i, v.x, v.y);
    split2_store(hi, lo, i + 2, v.z, v.w);
}

// ----------------------------------------------------------------------------
// Embedding + sinusoidal PE  (writes fp32 x and bf16 hi/lo split)
// ----------------------------------------------------------------------------
__global__ void __launch_bounds__(256) embed_kernel(const int* __restrict__ ids,
                                                    const float* __restrict__ emb)
{
    int t = blockIdx.x;
    int pos = t & (SEQL - 1);
    const float* e = emb + (size_t)ids[t] * DMODEL;
    size_t base = (size_t)t * DMODEL;
    const float klog = -9.210340371976184f / (float)DMODEL;
    for (int p = threadIdx.x; p < DMODEL / 2; p += 256) {
        int d0 = 2 * p;
        float freq = expf((float)d0 * klog);
        float ang = (float)pos * freq;
        float v0 = e[d0] + sinf(ang);
        float v1 = e[d0 + 1] + cosf(ang);
        g_x[base + d0] = v0;
        g_x[base + d0 + 1] = v1;
        split2_store(g_xh, g_xl, base + d0, v0, v1);
    }
}

// ----------------------------------------------------------------------------
// Split-bf16 HMMA GEMM, cp.async 2-stage pipelined.
// C[M,Nfull] = A[M,K] @ W[K,Nfull] + bias
// CTA tile 128x128x32, 256 threads = 8 warps (4m x 2n), warp tile 32x64.
// ----------------------------------------------------------------------------
#define BK   32
#define APAD 40     // bf16; 80B rows, 16B-aligned padding (cp.async-compatible)
#define BPAD 136    // bf16; 272B rows

#define A_ELEMS (128 * APAD)            // 5120
#define B_ELEMS (BK * BPAD)             // 4352
#define ST_AH   0
#define ST_AL   (A_ELEMS)
#define ST_BH   (2 * A_ELEMS)
#define ST_BL   (2 * A_ELEMS + B_ELEMS)
#define STAGE_ELEMS (2 * A_ELEMS + 2 * B_ELEMS)        // 18944 bf16
#define STAGE_BYTES (STAGE_ELEMS * 2)                  // 37888 B
#define SMEM_GEMM (2 * STAGE_BYTES)                    // 75776 B

template<int RELU, int WF32, int WSPLIT>
__device__ __forceinline__ void gemm_body(
    const bf16* __restrict__ Ah_g, const bf16* __restrict__ Al_g,
    const bf16* __restrict__ Wh_g, const bf16* __restrict__ Wl_g,
    const float* __restrict__ bias,
    float* __restrict__ Cf, bf16* __restrict__ Ch, bf16* __restrict__ Cl,
    int Nfull, int K, int bx, int by, float oscale)
{
    extern __shared__ bf16 smem[];
    const uint32_t sbase = smem_to_u32(smem);

    const int tid = threadIdx.x;
    const int wid = tid >> 5, lane = tid & 31;
    const int warp_m = wid >> 1;
    const int warp_n = wid & 1;
    const int m0 = by * 128, n0 = bx * 128;

    // Per-thread load slots (fixed across chunks)
    const int a_r0 = tid >> 2, a_sg = (tid & 3) * 8;          // A slot 0: rows 0..63
    const int a_r1 = a_r0 + 64;                               // A slot 1: rows 64..127
    const int b_r0 = tid >> 4, b_sg = (tid & 15) * 8;         // B slot 0: k-rows 0..15
    const int b_r1 = b_r0 + 16;                               // B slot 1: k-rows 16..31

    const int nchunk = K / BK;

    auto issue_loads = [&](int c, int stg) {
        const int k0 = c * BK;
        const uint32_t st = sbase + stg * STAGE_BYTES;
        size_t ga0 = (size_t)(m0 + a_r0) * K + k0 + a_sg;
        size_t ga1 = (size_t)(m0 + a_r1) * K + k0 + a_sg;
        cp16(st + (ST_AH + a_r0 * APAD + a_sg) * 2, Ah_g + ga0);
        cp16(st + (ST_AH + a_r1 * APAD + a_sg) * 2, Ah_g + ga1);
        cp16(st + (ST_AL + a_r0 * APAD + a_sg) * 2, Al_g + ga0);
        cp16(st + (ST_AL + a_r1 * APAD + a_sg) * 2, Al_g + ga1);
        size_t gb0 = (size_t)(k0 + b_r0) * Nfull + n0 + b_sg;
        size_t gb1 = (size_t)(k0 + b_r1) * Nfull + n0 + b_sg;
        cp16(st + (ST_BH + b_r0 * BPAD + b_sg) * 2, Wh_g + gb0);
        cp16(st + (ST_BH + b_r1 * BPAD + b_sg) * 2, Wh_g + gb1);
        cp16(st + (ST_BL + b_r0 * BPAD + b_sg) * 2, Wl_g + gb0);
        cp16(st + (ST_BL + b_r1 * BPAD + b_sg) * 2, Wl_g + gb1);
    };

    float acc[2][8][4];
#pragma unroll
    for (int mt = 0; mt < 2; mt++)
#pragma unroll
        for (int nt = 0; nt < 8; nt++)
#pragma unroll
            for (int r = 0; r < 4; r++) acc[mt][nt][r] = 0.f;

    issue_loads(0, 0);
    cp_commit();

    for (int c = 0; c < nchunk; c++) {
        const int stg = c & 1;
        if (c + 1 < nchunk) {
            issue_loads(c + 1, stg ^ 1);
            cp_commit();
            cp_wait<1>();
        } else {
            cp_wait<0>();
        }
        __syncthreads();

        const bf16* sA = smem + stg * STAGE_ELEMS;
        const bf16* sBh_ = sA + ST_BH;
        const bf16* sBl_ = sA + ST_BL;
        const bf16* sAh_ = sA + ST_AH;
        const bf16* sAl_ = sA + ST_AL;

#pragma unroll
        for (int kk = 0; kk < BK; kk += 16) {
            uint32_t afh[2][4], afl[2][4];
#pragma unroll
            for (int mt = 0; mt < 2; mt++) {
                int row = warp_m * 32 + mt * 16 + (lane & 15);
                int col = kk + ((lane >> 4) << 3);
                ldsm4(afh[mt], smem_to_u32(&sAh_[row * APAD + col]));
                ldsm4(afl[mt], smem_to_u32(&sAl_[row * APAD + col]));
            }
            {   // B-hi fragments: passes Ah*Bh and Al*Bh
                uint32_t bf[4][4];
#pragma unroll
                for (int p = 0; p < 4; p++) {
                    int krow = kk + (lane & 15);
                    int col = warp_n * 64 + p * 16 + ((lane >> 4) << 3);
                    ldsm4t(bf[p], smem_to_u32(&sBh_[krow * BPAD + col]));
                }
#pragma unroll
                for (int mt = 0; mt < 2; mt++)
#pragma unroll
                    for (int nt = 0; nt < 8; nt++)
                        mma16816(acc[mt][nt], afh[mt], &bf[nt >> 1][(nt & 1) * 2]);
#pragma unroll
                for (int mt = 0; mt < 2; mt++)
#pragma unroll
                    for (int nt = 0; nt < 8; nt++)
                        mma16816(acc[mt][nt], afl[mt], &bf[nt >> 1][(nt & 1) * 2]);
            }
            {   // B-lo fragments: pass Ah*Bl
                uint32_t bf[4][4];
#pragma unroll
                for (int p = 0; p < 4; p++) {
                    int krow = kk + (lane & 15);
                    int col = warp_n * 64 + p * 16 + ((lane >> 4) << 3);
                    ldsm4t(bf[p], smem_to_u32(&sBl_[krow * BPAD + col]));
                }
#pragma unroll
                for (int mt = 0; mt < 2; mt++)
#pragma unroll
                    for (int nt = 0; nt < 8; nt++)
                        mma16816(acc[mt][nt], afh[mt], &bf[nt >> 1][(nt & 1) * 2]);
            }
        }
        __syncthreads();
    }

    const int rb = m0 + warp_m * 32;
    const int cb0 = n0 + warp_n * 64;
#pragma unroll
    for (int mt = 0; mt < 2; mt++)
#pragma unroll
        for (int nt = 0; nt < 8; nt++)
#pragma unroll
            for (int hh = 0; hh < 2; hh++) {
                int row = rb + mt * 16 + (lane >> 2) + hh * 8;
                int col = cb0 + nt * 8 + (lane & 3) * 2;
                float v0 = acc[mt][nt][hh * 2 + 0] + bias[col];
                float v1 = acc[mt][nt][hh * 2 + 1] + bias[col + 1];
                if (RELU) { v0 = fmaxf(v0, 0.f); v1 = fmaxf(v1, 0.f); }
                v0 *= oscale; v1 *= oscale;
                size_t oi = (size_t)row * Nfull + col;
                if (WF32)   *(float2*)(Cf + oi) = make_float2(v0, v1);
                if (WSPLIT) split2_store(Ch, Cl, oi, v0, v1);
            }
}

template<int RELU, int WF32, int WSPLIT>
__global__ void __launch_bounds__(256) gemm_sb(
    const bf16* __restrict__ Ah_g, const bf16* __restrict__ Al_g,
    const bf16* __restrict__ Wh_g, const bf16* __restrict__ Wl_g,
    const float* __restrict__ bias,
    float* __restrict__ Cf, bf16* __restrict__ Ch, bf16* __restrict__ Cl,
    int Nfull, int K)
{
    gemm_body<RELU, WF32, WSPLIT>(Ah_g, Al_g, Wh_g, Wl_g, bias, Cf, Ch, Cl,
                                  Nfull, K, blockIdx.x, blockIdx.y, 1.0f);
}

// Fused QKV: blockIdx.z selects weight/output triple; writes split bf16.
__global__ void __launch_bounds__(256) gemm_qkv(
    const bf16* __restrict__ Wqh, const bf16* __restrict__ Wql, const float* __restrict__ Bq,
    const bf16* __restrict__ Wkh, const bf16* __restrict__ Wkl, const float* __restrict__ Bk,
    const bf16* __restrict__ Wvh, const bf16* __restrict__ Wvl, const float* __restrict__ Bv)
{
    const bf16 *wh, *wl; const float* bias; bf16 *ch, *cl; float sc;
    if (blockIdx.z == 0)      { wh = Wqh; wl = Wql; bias = Bq; ch = g_qh; cl = g_ql; sc = 0.125f; }
    else if (blockIdx.z == 1) { wh = Wkh; wl = Wkl; bias = Bk; ch = g_kh; cl = g_kl; sc = 1.0f; }
    else                      { wh = Wvh; wl = Wvl; bias = Bv; ch = g_vh; cl = g_vl; sc = 1.0f; }
    gemm_body<0, 0, 1>(g_xh, g_xl, wh, wl, bias, nullptr, ch, cl,
                       DMODEL, DMODEL, blockIdx.x, blockIdx.y, sc);
}

// ----------------------------------------------------------------------------
// Tensor-core flash attention. Block = (b,h, 64 q-rows), 4 warps x 16 rows.
// ----------------------------------------------------------------------------
#define ATPAD 72

__global__ void __launch_bounds__(128) attn_mma(const int* __restrict__ mask)
{
    const int bh = blockIdx.x;
    const int b = bh / NHEAD, h = bh % NHEAD;
    const int qt = blockIdx.y;
    const int tid = threadIdx.x, wid = tid >> 5, lane = tid & 31;
    const int c0 = (lane & 3) * 2;

    __shared__ bf16 sKh[64 * ATPAD], sKl[64 * ATPAD];
    __shared__ bf16 sVh[64 * ATPAD], sVl[64 * ATPAD];
    __shared__ float sneg[64];

    {
        size_t qbase = ((size_t)(b * SEQL + qt * 64)) * DMODEL + h * DKHEAD;
#pragma unroll
        for (int it = 0; it < 4; it++) {
            int slot = it * 128 + tid;
            int r = slot >> 3, c = (slot & 7) * 8;
            size_t gi = qbase + (size_t)r * DMODEL + c;
            *(uint4*)&sKh[r * ATPAD + c] = *(const uint4*)(g_qh + gi);
            *(uint4*)&sKl[r * ATPAD + c] = *(const uint4*)(g_ql + gi);
        }
    }
    __syncthreads();
    uint32_t qfh[4][4], qfl[4][4];
#pragma unroll
    for (int ks = 0; ks < 4; ks++) {
        int row = wid * 16 + (lane & 15);
        int col = ks * 16 + ((lane >> 4) << 3);
        ldsm4(qfh[ks], smem_to_u32(&sKh[row * ATPAD + col]));
        ldsm4(qfl[ks], smem_to_u32(&sKl[row * ATPAD + col]));
    }
    __syncthreads();

    float o[8][4];
#pragma unroll
    for (int nt = 0; nt < 8; nt++)
#pragma unroll
        for (int r = 0; r < 4; r++) o[nt][r] = 0.f;
    float m0 = -1e30f, m1 = -1e30f, sum0 = 0.f, sum1 = 0.f;

    for (int kt = 0; kt < SEQL / 64; kt++) {
        size_t kb = ((size_t)(b * SEQL + kt * 64)) * DMODEL + h * DKHEAD;
#pragma unroll
        for (int it = 0; it < 4; it++) {
            int slot = it * 128 + tid;
            int r = slot >> 3, c = (slot & 7) * 8;
            size_t gi = kb + (size_t)r * DMODEL + c;
            *(uint4*)&sKh[r * ATPAD + c] = *(const uint4*)(g_kh + gi);
            *(uint4*)&sKl[r * ATPAD + c] = *(const uint4*)(g_kl + gi);
            *(uint4*)&sVh[r * ATPAD + c] = *(const uint4*)(g_vh + gi);
            *(uint4*)&sVl[r * ATPAD + c] = *(const uint4*)(g_vl + gi);
        }
        if (tid < 64) sneg[tid] = (mask[b * SEQL + kt * 64 + tid] == 0) ? -1e9f : 0.f;
        __syncthreads();

        float S[8][4];
#pragma unroll
        for (int nt = 0; nt < 8; nt++)
#pragma unroll
            for (int r = 0; r < 4; r++) S[nt][r] = 0.f;
#pragma unroll
        for (int ks = 0; ks < 4; ks++) {
            uint32_t kbh[4][4], kbl[4][4];
#pragma unroll
            for (int g = 0; g < 4; g++) {
                int nrow = g * 16 + (lane & 7) + ((lane & 16) ? 8 : 0);
                int ncol = ks * 16 + ((lane & 8) ? 8 : 0);
                ldsm4(kbh[g], smem_to_u32(&sKh[nrow * ATPAD + ncol]));
                ldsm4(kbl[g], smem_to_u32(&sKl[nrow * ATPAD + ncol]));
            }
#pragma unroll
            for (int nt = 0; nt < 8; nt++) {
                const uint32_t* bh_ = &kbh[nt >> 1][(nt & 1) * 2];
                const uint32_t* bl_ = &kbl[nt >> 1][(nt & 1) * 2];
                mma16816(S[nt], qfh[ks], bh_);
                mma16816(S[nt], qfl[ks], bh_);
                mma16816(S[nt], qfh[ks], bl_);
            }
        }

        float mx0 = -1e30f, mx1 = -1e30f;
#pragma unroll
        for (int nt = 0; nt < 8; nt++) {
            float n0 = sneg[nt * 8 + c0], n1 = sneg[nt * 8 + c0 + 1];
            S[nt][0] += n0; S[nt][1] += n1; S[nt][2] += n0; S[nt][3] += n1;
            mx0 = fmaxf(mx0, fmaxf(S[nt][0], S[nt][1]));
            mx1 = fmaxf(mx1, fmaxf(S[nt][2], S[nt][3]));
        }
        mx0 = fmaxf(mx0, __shfl_xor_sync(0xffffffffu, mx0, 1));
        mx0 = fmaxf(mx0, __shfl_xor_sync(0xffffffffu, mx0, 2));
        mx1 = fmaxf(mx1, __shfl_xor_sync(0xffffffffu, mx1, 1));
        mx1 = fmaxf(mx1, __shfl_xor_sync(0xffffffffu, mx1, 2));
        float nm0 = fmaxf(m0, mx0), nm1 = fmaxf(m1, mx1);
        float cr0 = __expf(m0 - nm0), cr1 = __expf(m1 - nm1);
        m0 = nm0; m1 = nm1;
        sum0 *= cr0; sum1 *= cr1;
#pragma unroll
        for (int nt = 0; nt < 8; nt++) {
            o[nt][0] *= cr0; o[nt][1] *= cr0; o[nt][2] *= cr1; o[nt][3] *= cr1;
        }

        float ls0 = 0.f, ls1 = 0.f;
#pragma unroll
        for (int ks = 0; ks < 4; ks++) {
            const int j = 2 * ks, j1 = 2 * ks + 1;
            float p00 = __expf(S[j][0] - m0),  p01 = __expf(S[j][1] - m0);
            float p10 = __expf(S[j][2] - m1),  p11 = __expf(S[j][3] - m1);
            float r00 = __expf(S[j1][0] - m0), r01 = __expf(S[j1][1] - m0);
            float r10 = __expf(S[j1][2] - m1), r11 = __expf(S[j1][3] - m1);
            ls0 += p00 + p01 + r00 + r01;
            ls1 += p10 + p11 + r10 + r11;
            uint32_t ah[4], al[4];
            splitpack(p00, p01, ah[0], al[0]);
            splitpack(p10, p11, ah[1], al[1]);
            splitpack(r00, r01, ah[2], al[2]);
            splitpack(r10, r11, ah[3], al[3]);
            uint32_t vbh[4][4], vbl[4][4];
#pragma unroll
            for (int g = 0; g < 4; g++) {
                int vrow = ks * 16 + (lane & 15);
                int vcol = g * 16 + ((lane >> 4) << 3);
                ldsm4t(vbh[g], smem_to_u32(&sVh[vrow * ATPAD + vcol]));
                ldsm4t(vbl[g], smem_to_u32(&sVl[vrow * ATPAD + vcol]));
            }
#pragma unroll
            for (int nt = 0; nt < 8; nt++) {
                const uint32_t* bh_ = &vbh[nt >> 1][(nt & 1) * 2];
                const uint32_t* bl_ = &vbl[nt >> 1][(nt & 1) * 2];
                mma16816(o[nt], ah, bh_);
                mma16816(o[nt], al, bh_);
                mma16816(o[nt], ah, bl_);
            }
        }
        ls0 += __shfl_xor_sync(0xffffffffu, ls0, 1);
        ls0 += __shfl_xor_sync(0xffffffffu, ls0, 2);
        ls1 += __shfl_xor_sync(0xffffffffu, ls1, 1);
        ls1 += __shfl_xor_sync(0xffffffffu, ls1, 2);
        sum0 += ls0; sum1 += ls1;
        __syncthreads();
    }

    float inv0 = 1.f / sum0, inv1 = 1.f / sum1;
    int row0 = qt * 64 + wid * 16 + (lane >> 2);
    size_t ob0 = ((size_t)(b * SEQL + row0)) * DMODEL + h * DKHEAD;
    size_t ob1 = ob0 + (size_t)8 * DMODEL;
#pragma unroll
    for (int nt = 0; nt < 8; nt++) {
        int col = nt * 8 + c0;
        split2_store(g_ah, g_al, ob0 + col, o[nt][0] * inv0, o[nt][1] * inv0);
        split2_store(g_ah, g_al, ob1 + col, o[nt][2] * inv1, o[nt][3] * inv1);
    }
}

// ----------------------------------------------------------------------------
// Residual add + LayerNorm (in-place into g_x + bf16 split). One block/token.
// ----------------------------------------------------------------------------
__global__ void __launch_bounds__(256) add_ln_kernel(const float* __restrict__ y,
                                                     const float* __restrict__ gam,
                                                     const float* __restrict__ bet)
{
    int t = blockIdx.x;
    int tid = threadIdx.x;
    __shared__ float red[32];
    size_t base = (size_t)t * DMODEL;

    float2 z0, z1 = make_float2(0.f, 0.f);
    const bool has1 = (tid < DMODEL / 2 - 256);
    {
        float2 a = *(const float2*)(g_x + base + 2 * tid);
        float2 bb = *(const float2*)(y + base + 2 * tid);
        z0 = make_float2(a.x + bb.x, a.y + bb.y);
        if (has1) {
            float2 a1 = *(const float2*)(g_x + base + 2 * (tid + 256));
            float2 b1 = *(const float2*)(y + base + 2 * (tid + 256));
            z1 = make_float2(a1.x + b1.x, a1.y + b1.y);
        }
    }
    float s = z0.x + z0.y + z1.x + z1.y;
#pragma unroll
    for (int off = 16; off; off >>= 1) s += __shfl_xor_sync(0xffffffffu, s, off);
    if ((tid & 31) == 0) red[tid >> 5] = s;
    __syncthreads();
    if (tid < 32) {
        float v = (tid < 8) ? red[tid] : 0.f;
#pragma unroll
        for (int off = 4; off; off >>= 1) v += __shfl_xor_sync(0xffffffffu, v, off);
        if (tid == 0) red[0] = v;
    }
    __syncthreads();
    float mu = red[0] * (1.f / DMODEL);
    __syncthreads();

    float sq = 0.f;
    { float d0 = z0.x - mu, d1 = z0.y - mu; sq = fmaf(d0, d0, fmaf(d1, d1, sq)); }
    if (has1) { float d0 = z1.x - mu, d1 = z1.y - mu; sq = fmaf(d0, d0, fmaf(d1, d1, sq)); }
#pragma unroll
    for (int off = 16; off; off >>= 1) sq += __shfl_xor_sync(0xffffffffu, sq, off);
    if ((tid & 31) == 0) red[tid >> 5] = sq;
    __syncthreads();
    if (tid < 32) {
        float v = (tid < 8) ? red[tid] : 0.f;
#pragma unroll
        for (int off = 4; off; off >>= 1) v += __shfl_xor_sync(0xffffffffu, v, off);
        if (tid == 0) red[0] = v;
    }
    __syncthreads();
    float rstd = rsqrtf(red[0] * (1.f / DMODEL) + 1e-5f);

    {
        int d = 2 * tid;
        float n0 = (z0.x - mu) * rstd * gam[d] + bet[d];
        float n1 = (z0.y - mu) * rstd * gam[d + 1] + bet[d + 1];
        *(float2*)(g_x + base + d) = make_float2(n0, n1);
        split2_store(g_xh, g_xl, base + d, n0, n1);
    }
    if (has1) {
        int d = 2 * (tid + 256);
        float n0 = (z1.x - mu) * rstd * gam[d] + bet[d];
        float n1 = (z1.y - mu) * rstd * gam[d + 1] + bet[d + 1];
        *(float2*)(g_x + base + d) = make_float2(n0, n1);
        split2_store(g_xh, g_xl, base + d, n0, n1);
    }
}

// ----------------------------------------------------------------------------
// Classifier
// ----------------------------------------------------------------------------
__global__ void cls_kernel(const float* __restrict__ w,
                           const float* __restrict__ cb,
                           float* __restrict__ out)
{
    int t = threadIdx.x;
    if (t >= BATCH * NCLS) return;
    int b = t / NCLS, c = t % NCLS;
    const float* xp = g_x + (size_t)b * SEQL * DMODEL;
    float s = cb[c];
    for (int d = 0; d < DMODEL; d++) s = fmaf(xp[d], w[d * NCLS + c], s);
    out[t] = s;
}

// ----------------------------------------------------------------------------
// Launch
// ----------------------------------------------------------------------------
extern "C" void kernel_launch(void* const* d_in, const int* in_sizes, int n_in,
                              void* d_out, int out_size)
{
    (void)in_sizes; (void)n_in; (void)out_size;
    const int*   ids  = (const int*)d_in[0];
    const int*   mask = (const int*)d_in[1];
    const float* emb  = (const float*)d_in[2];
    const float* wq = (const float*)d_in[3],  *bq = (const float*)d_in[4];
    const float* wk = (const float*)d_in[5],  *bk = (const float*)d_in[6];
    const float* wv = (const float*)d_in[7],  *bv = (const float*)d_in[8];
    const float* wo = (const float*)d_in[9],  *bo = (const float*)d_in[10];
    const float* g1 = (const float*)d_in[11], *bb1 = (const float*)d_in[12];
    const float* w1 = (const float*)d_in[13], *b1 = (const float*)d_in[14];
    const float* w2 = (const float*)d_in[15], *b2 = (const float*)d_in[16];
    const float* g2 = (const float*)d_in[17], *bb2 = (const float*)d_in[18];
    const float* cw = (const float*)d_in[19], *cb = (const float*)d_in[20];
    float* out = (float*)d_out;

    cudaFuncSetAttribute(gemm_qkv, cudaFuncAttributeMaxDynamicSharedMemorySize, SMEM_GEMM);
    cudaFuncSetAttribute(gemm_sb<0,1,0>, cudaFuncAttributeMaxDynamicSharedMemorySize, SMEM_GEMM);
    cudaFuncSetAttribute(gemm_sb<1,0,1>, cudaFuncAttributeMaxDynamicSharedMemorySize, SMEM_GEMM);

    bf16 *wqh, *wql, *wkh, *wkl, *wvh, *wvl, *woh, *wol, *w1h, *w1l, *w2h, *w2l;
    { void* p;
      cudaGetSymbolAddress(&p, g_wqh); wqh = (bf16*)p; cudaGetSymbolAddress(&p, g_wql); wql = (bf16*)p;
      cudaGetSymbolAddress(&p, g_wkh); wkh = (bf16*)p; cudaGetSymbolAddress(&p, g_wkl); wkl = (bf16*)p;
      cudaGetSymbolAddress(&p, g_wvh); wvh = (bf16*)p; cudaGetSymbolAddress(&p, g_wvl); wvl = (bf16*)p;
      cudaGetSymbolAddress(&p, g_woh); woh = (bf16*)p; cudaGetSymbolAddress(&p, g_wol); wol = (bf16*)p;
      cudaGetSymbolAddress(&p, g_w1h); w1h = (bf16*)p; cudaGetSymbolAddress(&p, g_w1l); w1l = (bf16*)p;
      cudaGetSymbolAddress(&p, g_w2h); w2h = (bf16*)p; cudaGetSymbolAddress(&p, g_w2l); w2l = (bf16*)p;
    }
    bf16 *xh, *xl, *ah, *al, *fh, *fl;
    { void* p;
      cudaGetSymbolAddress(&p, g_xh); xh = (bf16*)p; cudaGetSymbolAddress(&p, g_xl); xl = (bf16*)p;
      cudaGetSymbolAddress(&p, g_ah); ah = (bf16*)p; cudaGetSymbolAddress(&p, g_al); al = (bf16*)p;
      cudaGetSymbolAddress(&p, g_fh); fh = (bf16*)p; cudaGetSymbolAddress(&p, g_fl); fl = (bf16*)p;
    }
    float *ptmp;
    { void* p; cudaGetSymbolAddress(&p, g_tmp); ptmp = (float*)p; }

    const int nDD = NLAYER * DMODEL * DMODEL;
    const int nDF = NLAYER * DMODEL * FFDIM;
    const int tb = 256;

    dim3 gD(DMODEL / 128, TOK / 128);        // (6, 64)
    dim3 gQKV(DMODEL / 128, TOK / 128, 3);   // (6, 64, 3)
    dim3 gF(FFDIM / 128, TOK / 128);         // (24, 64)
    dim3 gA(BATCH * NHEAD, SEQL / 64);       // (96, 16)

    split_kernel<<<nDD / 4 / tb, tb>>>(wq, wqh, wql, nDD);
    split_kernel<<<nDD / 4 / tb, tb>>>(wk, wkh, wkl, nDD);
    split_kernel<<<nDD / 4 / tb, tb>>>(wv, wvh, wvl, nDD);
    embed_kernel<<<TOK, 256>>>(ids, emb);
    split_kernel<<<nDD / 4 / tb, tb>>>(wo, woh, wol, nDD);

    for (int l = 0; l < NLAYER; l++) {
        size_t oD = (size_t)l * DMODEL * DMODEL;
        size_t oF = (size_t)l * DMODEL * FFDIM;

        gemm_qkv<<<gQKV, 256, SMEM_GEMM>>>(wqh + oD, wql + oD, bq + l * DMODEL,
                                           wkh + oD, wkl + oD, bk + l * DMODEL,
                                           wvh + oD, wvl + oD, bv + l * DMODEL);

        attn_mma<<<gA, 128>>>(mask);

        if (l == 0) {
            split_kernel<<<nDF / 4 / tb, tb>>>(w1, w1h, w1l, nDF);
            split_kernel<<<nDF / 4 / tb, tb>>>(w2, w2h, w2l, nDF);
        }

        gemm_sb<0,1,0><<<gD, 256, SMEM_GEMM>>>(ah, al, woh + oD, wol + oD, bo + l * DMODEL,
                                               ptmp, nullptr, nullptr, DMODEL, DMODEL);
        add_ln_kernel<<<TOK, 256>>>(ptmp, g1 + l * DMODEL, bb1 + l * DMODEL);

        gemm_sb<1,0,1><<<gF, 256, SMEM_GEMM>>>(xh, xl, w1h + oF, w1l + oF, b1 + l * FFDIM,
                                               nullptr, fh, fl, FFDIM, DMODEL);
        gemm_sb<0,1,0><<<gD, 256, SMEM_GEMM>>>(fh, fl, w2h + oF, w2l + oF, b2 + l * DMODEL,
                                               ptmp, nullptr, nullptr, DMODEL, FFDIM);
        add_ln_kernel<<<TOK, 256>>>(ptmp, g2 + l * DMODEL, bb2 + l * DMODEL);
    }

    cls_kernel<<<1, 128>>>(cw, cb, out);
}